// round 1
// baseline (speedup 1.0000x reference)
#include <cuda_runtime.h>
#include <cstdint>
#include <math.h>

typedef unsigned long long ull;

#define B_  16
#define C_  1024
#define P_  512
#define HW_ 1024
#define G_  8

// ---------------- scratch (static device globals; no allocation) ----------------
__device__ float d_t[(size_t)B_ * P_ * HW_];   // 32 MB
__device__ float d_p[(size_t)B_ * P_ * HW_];   // 32 MB
__device__ float d_g[(size_t)B_ * P_ * HW_];   // 32 MB
__device__ float d_z[(size_t)B_ * C_ * HW_];   // 64 MB
__device__ float d_c[B_ * G_ * 4];             // poly coefficients per (b,g)
__device__ float d_stats[B_ * G_ * 2];         // mean, rstd per (b,g)

// ---------------- packed f32x2 helpers (full-rate fp32 on sm_103a) ----------------
__device__ __forceinline__ ull f2fma(ull a, ull b, ull c) {
    ull d;
    asm("fma.rn.f32x2 %0, %1, %2, %3;" : "=l"(d) : "l"(a), "l"(b), "l"(c));
    return d;
}
__device__ __forceinline__ void f2unpack(ull v, float& lo, float& hi) {
    asm("mov.b64 {%0, %1}, %2;" : "=f"(lo), "=f"(hi) : "l"(v));
}

// =====================================================================
// Kernel 1: fused t/p/g GEMM.
//   t[b,o,n] = sum_c Wt[o,c] * x[b,c,n]   (same for p with Wp, g with Wg)
// Block: 64(M) x 64(N) tile for ONE batch, all 3 weights (X tile reused 3x).
// Inner loop: LDS.64 of duplicated W pairs + fma.rn.f32x2 (n-pair accumulators).
// =====================================================================
__global__ void __launch_bounds__(256) k_gemm3(
    const float* __restrict__ x, const float* __restrict__ Wt,
    const float* __restrict__ Wp, const float* __restrict__ Wg)
{
    extern __shared__ char sm[];
    float*  Xs  = (float*)sm;                  // [32][64]  (8 KB)
    float2* Wsd = (float2*)(sm + 32 * 64 * 4); // [3][64][32] duplicated (48 KB)

    const int b   = blockIdx.z;
    const int m0  = blockIdx.y * 64;
    const int n0  = blockIdx.x * 64;
    const int tid = threadIdx.x;
    const int tx  = tid & 15;   // N: cols tx*4 .. tx*4+3
    const int ty  = tid >> 4;   // M: rows ty*4 .. ty*4+3

    const float* Wl[3] = {Wt, Wp, Wg};

    ull acc[3][4][2];
#pragma unroll
    for (int w = 0; w < 3; w++)
#pragma unroll
        for (int i = 0; i < 4; i++) { acc[w][i][0] = 0ULL; acc[w][i][1] = 0ULL; }

    const float* xb = x + (size_t)b * C_ * HW_ + n0;

    for (int k0 = 0; k0 < C_; k0 += 32) {
        // ---- load X tile [32k x 64n] ----
#pragma unroll
        for (int s = 0; s < 2; s++) {
            int slot = tid + s * 256;           // 0..511 float4 slots
            int r  = slot >> 4;                 // 0..31
            int c4 = (slot & 15) << 2;          // 0..60
            *(float4*)&Xs[r * 64 + c4] =
                *(const float4*)&xb[(size_t)(k0 + r) * HW_ + c4];
        }
        // ---- load W tiles [64m x 32k] x3, store duplicated (w,w) pairs ----
#pragma unroll
        for (int w = 0; w < 3; w++) {
            const float* W = Wl[w];
#pragma unroll
            for (int s = 0; s < 2; s++) {
                int slot = tid + s * 256;       // 0..511
                int m  = slot >> 3;             // 0..63
                int k4 = (slot & 7) << 2;       // 0..28
                float4 v = *(const float4*)&W[(size_t)(m0 + m) * C_ + k0 + k4];
                float2* dst = &Wsd[(w * 64 + m) * 32 + k4];
                dst[0] = make_float2(v.x, v.x);
                dst[1] = make_float2(v.y, v.y);
                dst[2] = make_float2(v.z, v.z);
                dst[3] = make_float2(v.w, v.w);
            }
        }
        __syncthreads();

#pragma unroll 8
        for (int kk = 0; kk < 32; kk++) {
            ull xp0 = *(const ull*)&Xs[kk * 64 + tx * 4];
            ull xp1 = *(const ull*)&Xs[kk * 64 + tx * 4 + 2];
#pragma unroll
            for (int w = 0; w < 3; w++) {
#pragma unroll
                for (int i = 0; i < 4; i++) {
                    ull wd = *(const ull*)&Wsd[(w * 64 + ty * 4 + i) * 32 + kk];
                    acc[w][i][0] = f2fma(wd, xp0, acc[w][i][0]);
                    acc[w][i][1] = f2fma(wd, xp1, acc[w][i][1]);
                }
            }
        }
        __syncthreads();
    }

    float* outs[3] = {d_t, d_p, d_g};
#pragma unroll
    for (int w = 0; w < 3; w++) {
        float* o = outs[w] + ((size_t)b * P_ + m0 + ty * 4) * HW_ + n0 + tx * 4;
#pragma unroll
        for (int i = 0; i < 4; i++) {
            float4 v;
            f2unpack(acc[w][i][0], v.x, v.y);
            f2unpack(acc[w][i][1], v.z, v.w);
            *(float4*)&o[(size_t)i * HW_] = v;
        }
    }
}

// =====================================================================
// Kernel 2: attention moments.  One block per (b,g):
//   S[o] = sum_l p[l]^o * g[l]  over Lg=65536, o=0..3
//   d_c[bg][o] = alpha[o]^2 * S[o]
// =====================================================================
__global__ void __launch_bounds__(256) k_att()
{
    const int bg = blockIdx.x;                        // b*8 + g
    const float4* p4 = (const float4*)(d_p + (size_t)bg * 65536);
    const float4* g4 = (const float4*)(d_g + (size_t)bg * 65536);

    float s0 = 0.f, s1 = 0.f, s2 = 0.f, s3 = 0.f;
    for (int i = threadIdx.x; i < 16384; i += 256) {
        float4 pv = p4[i], gv = g4[i];
        {
            float pp = pv.x, gg = gv.x;
            s0 += gg; float t = pp * gg; s1 += t; t *= pp; s2 += t; t *= pp; s3 += t;
        }
        {
            float pp = pv.y, gg = gv.y;
            s0 += gg; float t = pp * gg; s1 += t; t *= pp; s2 += t; t *= pp; s3 += t;
        }
        {
            float pp = pv.z, gg = gv.z;
            s0 += gg; float t = pp * gg; s1 += t; t *= pp; s2 += t; t *= pp; s3 += t;
        }
        {
            float pp = pv.w, gg = gv.w;
            s0 += gg; float t = pp * gg; s1 += t; t *= pp; s2 += t; t *= pp; s3 += t;
        }
    }
#pragma unroll
    for (int off = 16; off > 0; off >>= 1) {
        s0 += __shfl_down_sync(0xffffffffu, s0, off);
        s1 += __shfl_down_sync(0xffffffffu, s1, off);
        s2 += __shfl_down_sync(0xffffffffu, s2, off);
        s3 += __shfl_down_sync(0xffffffffu, s3, off);
    }
    __shared__ float red[4][8];
    int lane = threadIdx.x & 31, wid = threadIdx.x >> 5;
    if (lane == 0) { red[0][wid] = s0; red[1][wid] = s1; red[2][wid] = s2; red[3][wid] = s3; }
    __syncthreads();
    if (threadIdx.x == 0) {
        float S0 = 0.f, S1 = 0.f, S2 = 0.f, S3 = 0.f;
#pragma unroll
        for (int i = 0; i < 8; i++) { S0 += red[0][i]; S1 += red[1][i]; S2 += red[2][i]; S3 += red[3][i]; }
        const float tg   = 2.0f * 1e-4f;
        const float beta = expf(-tg);
        d_c[bg * 4 + 0] = beta * S0;                                   // alpha0^2 = beta
        d_c[bg * 4 + 1] = beta * tg * S1;                              // alpha1^2 = 2g*beta
        d_c[bg * 4 + 2] = beta * (tg * tg * 0.5f) * S2;                // (2g)^2/2! * beta
        d_c[bg * 4 + 3] = beta * (tg * tg * tg * (1.f / 6.f)) * S3;    // (2g)^3/3! * beta
    }
}

// =====================================================================
// Kernel 3: y = c0 + c1*t + c2*t^2 + c3*t^3 (on the fly), then grouped GEMM
//   z[b, g*128+oc, n] = sum_i Wz[g,oc,i] * y[b,g,i,n]   (K=64)
// Block: one (b, g, 64-wide n-tile). f32x2 again with duplicated Wz in SMEM.
// =====================================================================
__global__ void __launch_bounds__(256) k_yz(const float* __restrict__ Wz)
{
    extern __shared__ char sm3[];
    float*  Ys  = (float*)sm3;                  // [64][64]  (16 KB)
    float2* Wzd = (float2*)(sm3 + 64 * 64 * 4); // [128][64] duplicated (64 KB)

    const int n0 = blockIdx.x * 64;
    const int g  = blockIdx.y;
    const int b  = blockIdx.z;
    const int tid = threadIdx.x;
    const int tx = tid & 15;    // n: tx*4..+3
    const int ty = tid >> 4;    // oc: ty*8..+7

    const int cbase = (b * 8 + g) * 4;
    const float c0 = d_c[cbase + 0], c1 = d_c[cbase + 1];
    const float c2 = d_c[cbase + 2], c3 = d_c[cbase + 3];

    // load Wz[g] duplicated
    const float* Wzg = Wz + g * (128 * 64);
    for (int s = tid; s < 8192; s += 256) {
        float w = Wzg[s];
        Wzd[s] = make_float2(w, w);
    }
    // build y tile from t
    const float* tb = d_t + ((size_t)b * P_ + g * 64) * HW_ + n0;
    for (int s = tid; s < 1024; s += 256) {     // 64 rows x 16 float4
        int i  = s >> 4;
        int c4 = (s & 15) << 2;
        float4 tv = *(const float4*)&tb[(size_t)i * HW_ + c4];
        float4 yv;
        yv.x = ((c3 * tv.x + c2) * tv.x + c1) * tv.x + c0;
        yv.y = ((c3 * tv.y + c2) * tv.y + c1) * tv.y + c0;
        yv.z = ((c3 * tv.z + c2) * tv.z + c1) * tv.z + c0;
        yv.w = ((c3 * tv.w + c2) * tv.w + c1) * tv.w + c0;
        *(float4*)&Ys[i * 64 + c4] = yv;
    }
    __syncthreads();

    ull acc[8][2];
#pragma unroll
    for (int j = 0; j < 8; j++) { acc[j][0] = 0ULL; acc[j][1] = 0ULL; }

#pragma unroll 8
    for (int kk = 0; kk < 64; kk++) {
        ull xp0 = *(const ull*)&Ys[kk * 64 + tx * 4];
        ull xp1 = *(const ull*)&Ys[kk * 64 + tx * 4 + 2];
#pragma unroll
        for (int j = 0; j < 8; j++) {
            ull wd = *(const ull*)&Wzd[(ty * 8 + j) * 64 + kk];
            acc[j][0] = f2fma(wd, xp0, acc[j][0]);
            acc[j][1] = f2fma(wd, xp1, acc[j][1]);
        }
    }

    float* zb = d_z + ((size_t)b * C_ + g * 128) * HW_ + n0;
#pragma unroll
    for (int j = 0; j < 8; j++) {
        float4 v;
        f2unpack(acc[j][0], v.x, v.y);
        f2unpack(acc[j][1], v.z, v.w);
        *(float4*)&zb[(size_t)(ty * 8 + j) * HW_ + tx * 4] = v;
    }
}

// =====================================================================
// Kernel 4: GroupNorm stats per (b,g) over 131072 elements of z.
// =====================================================================
__global__ void __launch_bounds__(256) k_gnstats()
{
    const int bg = blockIdx.x;
    const float4* z4 = (const float4*)(d_z + (size_t)bg * 131072);
    float s = 0.f, ss = 0.f;
    for (int i = threadIdx.x; i < 32768; i += 256) {
        float4 v = z4[i];
        s  += (v.x + v.y) + (v.z + v.w);
        ss += v.x * v.x + v.y * v.y + v.z * v.z + v.w * v.w;
    }
#pragma unroll
    for (int off = 16; off > 0; off >>= 1) {
        s  += __shfl_down_sync(0xffffffffu, s, off);
        ss += __shfl_down_sync(0xffffffffu, ss, off);
    }
    __shared__ float red[2][8];
    int lane = threadIdx.x & 31, wid = threadIdx.x >> 5;
    if (lane == 0) { red[0][wid] = s; red[1][wid] = ss; }
    __syncthreads();
    if (threadIdx.x == 0) {
        float S = 0.f, SS = 0.f;
#pragma unroll
        for (int i = 0; i < 8; i++) { S += red[0][i]; SS += red[1][i]; }
        const float invN = 1.0f / 131072.0f;
        float mean = S * invN;
        float var  = SS * invN - mean * mean;
        d_stats[bg * 2 + 0] = mean;
        d_stats[bg * 2 + 1] = rsqrtf(var + 1e-5f);
    }
}

// =====================================================================
// Kernel 5: out = (z - mean) * rstd * gn_w[ch] + gn_b[ch] + x
// =====================================================================
__global__ void __launch_bounds__(256) k_finish(
    const float* __restrict__ x, const float* __restrict__ gn_w,
    const float* __restrict__ gn_b, float* __restrict__ out)
{
    int i4 = blockIdx.x * 256 + threadIdx.x;
    if (i4 >= (B_ * C_ * HW_) / 4) return;
    size_t idx = (size_t)i4 * 4;
    int ch = (int)((idx >> 10) & 1023);
    int b  = (int)(idx >> 20);
    int bg = b * 8 + (ch >> 7);
    float mean = d_stats[bg * 2 + 0];
    float rstd = d_stats[bg * 2 + 1];
    float a = gn_w[ch] * rstd;
    float c = gn_b[ch] - mean * a;
    float4 zv = *(const float4*)&d_z[idx];
    float4 xv = *(const float4*)&x[idx];
    float4 o;
    o.x = zv.x * a + c + xv.x;
    o.y = zv.y * a + c + xv.y;
    o.z = zv.z * a + c + xv.z;
    o.w = zv.w * a + c + xv.w;
    *(float4*)&out[idx] = o;
}

// =====================================================================
extern "C" void kernel_launch(void* const* d_in, const int* in_sizes, int n_in,
                              void* d_out, int out_size)
{
    const float* x   = (const float*)d_in[0];
    const float* Wt  = (const float*)d_in[1];
    const float* Wp  = (const float*)d_in[2];
    const float* Wg  = (const float*)d_in[3];
    const float* Wz  = (const float*)d_in[4];
    const float* gnw = (const float*)d_in[5];
    const float* gnb = (const float*)d_in[6];
    float* out = (float*)d_out;

    cudaFuncSetAttribute(k_gemm3, cudaFuncAttributeMaxDynamicSharedMemorySize, 57344);
    cudaFuncSetAttribute(k_yz,    cudaFuncAttributeMaxDynamicSharedMemorySize, 81920);

    dim3 g1(HW_ / 64, P_ / 64, B_);        // 16 x 8 x 16
    k_gemm3<<<g1, 256, 57344>>>(x, Wt, Wp, Wg);

    k_att<<<B_ * G_, 256>>>();

    dim3 g3(HW_ / 64, G_, B_);             // 16 x 8 x 16
    k_yz<<<g3, 256, 81920>>>(Wz);

    k_gnstats<<<B_ * G_, 256>>>();

    int nblk5 = (B_ * C_ * HW_ / 4 + 255) / 256;
    k_finish<<<nblk5, 256>>>(x, gnw, gnb, out);
}

// round 3
// speedup vs baseline: 2.6626x; 2.6626x over previous
#include <cuda_runtime.h>
#include <cuda_bf16.h>
#include <cstdint>
#include <math.h>

typedef unsigned long long ull;

#define B_  16
#define C_  1024
#define P_  512
#define HW_ 1024
#define G_  8

// ---------------- scratch (static device globals; no allocation) ----------------
__device__ float d_t[(size_t)B_ * P_ * HW_];   // 32 MB
__device__ float d_p[(size_t)B_ * P_ * HW_];   // 32 MB
__device__ float d_g[(size_t)B_ * P_ * HW_];   // 32 MB
__device__ float d_z[(size_t)B_ * C_ * HW_];   // 64 MB
__device__ float d_c[B_ * G_ * 4];
__device__ float d_stats[B_ * G_ * 2];

// bf16 split operands
__device__ __nv_bfloat16 d_Whi[3u * 512u * 1024u];
__device__ __nv_bfloat16 d_Wlo[3u * 512u * 1024u];
__device__ __nv_bfloat16 d_XThi[(size_t)B_ * 1024u * 1024u];  // [b][n][k]
__device__ __nv_bfloat16 d_XTlo[(size_t)B_ * 1024u * 1024u];

// ---------------- PTX helpers ----------------
__device__ __forceinline__ uint32_t smem_u32(const void* p) {
    uint32_t a;
    asm("{ .reg .u64 t; cvta.to.shared.u64 t, %1; cvt.u32.u64 %0, t; }" : "=r"(a) : "l"(p));
    return a;
}
#define CP_ASYNC16(sa, ga) \
    asm volatile("cp.async.cg.shared.global [%0], [%1], 16;" :: "r"(sa), "l"(ga))
#define CP_COMMIT()   asm volatile("cp.async.commit_group;" ::: "memory")
#define CP_WAIT(n)    asm volatile("cp.async.wait_group %0;" :: "n"(n) : "memory")

__device__ __forceinline__ void ldsm_x4(uint32_t& r0, uint32_t& r1, uint32_t& r2, uint32_t& r3,
                                        uint32_t addr) {
    asm volatile("ldmatrix.sync.aligned.m8n8.x4.shared.b16 {%0,%1,%2,%3}, [%4];"
                 : "=r"(r0), "=r"(r1), "=r"(r2), "=r"(r3) : "r"(addr));
}
__device__ __forceinline__ void mma16816(float* c, const uint32_t* a, uint32_t b0, uint32_t b1) {
    asm volatile("mma.sync.aligned.m16n8k16.row.col.f32.bf16.bf16.f32 "
                 "{%0,%1,%2,%3}, {%4,%5,%6,%7}, {%8,%9}, {%0,%1,%2,%3};"
                 : "+f"(c[0]), "+f"(c[1]), "+f"(c[2]), "+f"(c[3])
                 : "r"(a[0]), "r"(a[1]), "r"(a[2]), "r"(a[3]), "r"(b0), "r"(b1));
}

// packed f32x2 (for k_yz)
__device__ __forceinline__ ull f2fma(ull a, ull b, ull c) {
    ull d; asm("fma.rn.f32x2 %0, %1, %2, %3;" : "=l"(d) : "l"(a), "l"(b), "l"(c)); return d;
}
__device__ __forceinline__ void f2unpack(ull v, float& lo, float& hi) {
    asm("mov.b64 {%0, %1}, %2;" : "=f"(lo), "=f"(hi) : "l"(v));
}

// =====================================================================
// Pre-pass A: W -> bf16 hi/lo
// =====================================================================
__global__ void __launch_bounds__(256) k_convW(
    const float* __restrict__ Wt, const float* __restrict__ Wp, const float* __restrict__ Wg)
{
    int w = blockIdx.y;
    const float* W = (w == 0) ? Wt : (w == 1) ? Wp : Wg;
    size_t idx = ((size_t)blockIdx.x * 256 + threadIdx.x) * 4;
    float4 v = *(const float4*)&W[idx];
    __nv_bfloat162 h01 = __floats2bfloat162_rn(v.x, v.y);
    __nv_bfloat162 h23 = __floats2bfloat162_rn(v.z, v.w);
    __nv_bfloat162 l01 = __floats2bfloat162_rn(v.x - __low2float(h01), v.y - __high2float(h01));
    __nv_bfloat162 l23 = __floats2bfloat162_rn(v.z - __low2float(h23), v.w - __high2float(h23));
    size_t o = (size_t)w * 524288u + idx;
    uint2 hv, lv;
    hv.x = *(uint32_t*)&h01; hv.y = *(uint32_t*)&h23;
    lv.x = *(uint32_t*)&l01; lv.y = *(uint32_t*)&l23;
    *(uint2*)(d_Whi + o) = hv;
    *(uint2*)(d_Wlo + o) = lv;
}

// =====================================================================
// Pre-pass B: X [b][k][n] fp32 -> XT [b][n][k] bf16 hi/lo (transpose+split)
// =====================================================================
__global__ void __launch_bounds__(256) k_transX(const float* __restrict__ x)
{
    __shared__ float Xs[32][132];
    int k0 = blockIdx.x * 32;
    int n0 = blockIdx.y * 128;
    int b  = blockIdx.z;
    int tid = threadIdx.x;
    const float* xb = x + ((size_t)b * 1024 + k0) * 1024 + n0;
#pragma unroll
    for (int i = 0; i < 4; i++) {
        int slot = tid + i * 256;
        int r  = slot >> 5;
        int c4 = (slot & 31) * 4;
        *(float4*)&Xs[r][c4] = *(const float4*)&xb[(size_t)r * 1024 + c4];
    }
    __syncthreads();
    int n  = tid >> 1;
    int kh = (tid & 1) * 16;
    uint32_t hi[8], lo[8];
#pragma unroll
    for (int j = 0; j < 8; j++) {
        float a  = Xs[kh + 2 * j][n];
        float bb = Xs[kh + 2 * j + 1][n];
        __nv_bfloat162 h = __floats2bfloat162_rn(a, bb);
        __nv_bfloat162 l = __floats2bfloat162_rn(a - __low2float(h), bb - __high2float(h));
        hi[j] = *(uint32_t*)&h;
        lo[j] = *(uint32_t*)&l;
    }
    size_t off = ((size_t)b * 1024 + n0 + n) * 1024 + k0 + kh;
    *(uint4*)(d_XThi + off)     = make_uint4(hi[0], hi[1], hi[2], hi[3]);
    *(uint4*)(d_XThi + off + 8) = make_uint4(hi[4], hi[5], hi[6], hi[7]);
    *(uint4*)(d_XTlo + off)     = make_uint4(lo[0], lo[1], lo[2], lo[3]);
    *(uint4*)(d_XTlo + off + 8) = make_uint4(lo[4], lo[5], lo[6], lo[7]);
}

// =====================================================================
// HMMA GEMM: D[128m x 128n] CTA tiles, warp 64x32, mma.sync m16n8k16 bf16,
// hi/lo split (Wh*Xh + Wh*Xl + Wl*Xh), fp32 accumulators.
// A = W[m][k] (K-major), B = XT[n][k] (K-major). cp.async double buffer.
// =====================================================================
#define NCH     32              // 1024 / BK, BK = 32
#define ROWB    80              // padded row stride bytes (32 bf16 + 8 pad)
#define TILE_B  10240           // 128 rows * 80 B
#define STG_B   40960           // 4 tiles per stage
#define OFF_AH  0
#define OFF_AL  10240
#define OFF_BH  20480
#define OFF_BL  30720

__device__ __forceinline__ void gemm_load_chunk(
    uint32_t sb, const __nv_bfloat16* gAh, const __nv_bfloat16* gAl,
    const __nv_bfloat16* gBh, const __nv_bfloat16* gBl, int k0, int tid)
{
    const __nv_bfloat16* srcs[4] = {gAh, gAl, gBh, gBl};
#pragma unroll
    for (int i = 0; i < 8; i++) {
        int unit = tid + i * 256;          // 0..2047
        int tile = unit >> 9;
        int rem  = unit & 511;
        int r = rem >> 2;
        int u = rem & 3;
        uint32_t dst = sb + (uint32_t)tile * TILE_B + (uint32_t)r * ROWB + (uint32_t)u * 16;
        const void* src = (const void*)(srcs[tile] + (size_t)r * 1024 + k0 + u * 8);
        CP_ASYNC16(dst, src);
    }
}

__global__ void __launch_bounds__(256, 2) k_gemm_mma()
{
    extern __shared__ char smraw[];
    uint32_t sbase = smem_u32(smraw);

    const int tid  = threadIdx.x;
    const int wid  = tid >> 5;
    const int lane = tid & 31;
    const int wm   = wid & 1;       // 0..1 -> m offset 64*wm
    const int wn   = wid >> 1;      // 0..3 -> n offset 32*wn

    const int n0 = blockIdx.x * 128;
    const int m0 = blockIdx.y * 128;
    const int z  = blockIdx.z;
    const int b  = z / 3;
    const int w  = z % 3;

    const __nv_bfloat16* gAh = d_Whi + (size_t)w * 524288u + (size_t)m0 * 1024;
    const __nv_bfloat16* gAl = d_Wlo + (size_t)w * 524288u + (size_t)m0 * 1024;
    const __nv_bfloat16* gBh = d_XThi + ((size_t)b * 1024 + n0) * 1024;
    const __nv_bfloat16* gBl = d_XTlo + ((size_t)b * 1024 + n0) * 1024;
    float* outp = (w == 0) ? d_t : (w == 1) ? d_p : d_g;

    float acc[4][4][4];
#pragma unroll
    for (int i = 0; i < 4; i++)
#pragma unroll
        for (int j = 0; j < 4; j++)
#pragma unroll
            for (int q = 0; q < 4; q++) acc[i][j][q] = 0.f;

    // ldmatrix lane address offsets (within a tile, before k-step add)
    // A: row = wm*64 + i*16 + (lane&15), kbyte = (lane>>4)*16
    const uint32_t aLane = (uint32_t)((wm * 64 + (lane & 15)) * ROWB + (lane >> 4) * 16);
    // B: group g=lane>>3: row = wn*32 + jp*16 + (g>>1)*8 + (lane&7), kbyte = (g&1)*16
    const int bg = lane >> 3;
    const uint32_t bLane = (uint32_t)((wn * 32 + (bg >> 1) * 8 + (lane & 7)) * ROWB + (bg & 1) * 16);

    // prologue
    gemm_load_chunk(sbase, gAh, gAl, gBh, gBl, 0, tid);
    CP_COMMIT();

    for (int j = 0; j < NCH; j++) {
        const uint32_t sb = sbase + (uint32_t)(j & 1) * STG_B;
        if (j + 1 < NCH) {
            gemm_load_chunk(sbase + (uint32_t)((j + 1) & 1) * STG_B,
                            gAh, gAl, gBh, gBl, (j + 1) * 32, tid);
            CP_COMMIT();
            CP_WAIT(1);
        } else {
            CP_WAIT(0);
        }
        __syncthreads();

#pragma unroll
        for (int s = 0; s < 2; s++) {
            const uint32_t kb = (uint32_t)s * 32;
            uint32_t A[4][4], Bv[4][2], Bl2[4][2];
#pragma unroll
            for (int i = 0; i < 4; i++)
                ldsm_x4(A[i][0], A[i][1], A[i][2], A[i][3],
                        sb + OFF_AH + aLane + (uint32_t)i * (16 * ROWB) + kb);
#pragma unroll
            for (int jp = 0; jp < 2; jp++) {
                ldsm_x4(Bv[jp * 2][0], Bv[jp * 2][1], Bv[jp * 2 + 1][0], Bv[jp * 2 + 1][1],
                        sb + OFF_BH + bLane + (uint32_t)jp * (16 * ROWB) + kb);
                ldsm_x4(Bl2[jp * 2][0], Bl2[jp * 2][1], Bl2[jp * 2 + 1][0], Bl2[jp * 2 + 1][1],
                        sb + OFF_BL + bLane + (uint32_t)jp * (16 * ROWB) + kb);
            }
            // Wh * Xh and Wh * Xl
#pragma unroll
            for (int i = 0; i < 4; i++)
#pragma unroll
                for (int jj = 0; jj < 4; jj++) {
                    mma16816(acc[i][jj], A[i], Bv[jj][0], Bv[jj][1]);
                    mma16816(acc[i][jj], A[i], Bl2[jj][0], Bl2[jj][1]);
                }
            // Wl * Xh
#pragma unroll
            for (int i = 0; i < 4; i++)
                ldsm_x4(A[i][0], A[i][1], A[i][2], A[i][3],
                        sb + OFF_AL + aLane + (uint32_t)i * (16 * ROWB) + kb);
#pragma unroll
            for (int i = 0; i < 4; i++)
#pragma unroll
                for (int jj = 0; jj < 4; jj++)
                    mma16816(acc[i][jj], A[i], Bv[jj][0], Bv[jj][1]);
        }
        __syncthreads();
    }

    // epilogue: d0,d1 -> row (lane>>2), cols (lane&3)*2,+1 ; d2,d3 -> row+8
    {
        const int rbase = m0 + wm * 64 + (lane >> 2);
        const int cbase = n0 + wn * 32 + (lane & 3) * 2;
        float* ob = outp + (size_t)b * 512 * 1024;
#pragma unroll
        for (int i = 0; i < 4; i++) {
#pragma unroll
            for (int jj = 0; jj < 4; jj++) {
                float2 v0 = make_float2(acc[i][jj][0], acc[i][jj][1]);
                float2 v1 = make_float2(acc[i][jj][2], acc[i][jj][3]);
                size_t r0 = (size_t)(rbase + i * 16) * 1024 + cbase + jj * 8;
                *(float2*)(ob + r0)               = v0;
                *(float2*)(ob + r0 + 8 * 1024)    = v1;
            }
        }
    }
}

// =====================================================================
// attention moments (1024 threads / block)
// =====================================================================
__global__ void __launch_bounds__(1024) k_att()
{
    const int bg = blockIdx.x;
    const float4* p4 = (const float4*)(d_p + (size_t)bg * 65536);
    const float4* g4 = (const float4*)(d_g + (size_t)bg * 65536);

    float s0 = 0.f, s1 = 0.f, s2 = 0.f, s3 = 0.f;
    for (int i = threadIdx.x; i < 16384; i += 1024) {
        float4 pv = p4[i], gv = g4[i];
        { float pp = pv.x, gg = gv.x; s0 += gg; float t = pp*gg; s1 += t; t *= pp; s2 += t; t *= pp; s3 += t; }
        { float pp = pv.y, gg = gv.y; s0 += gg; float t = pp*gg; s1 += t; t *= pp; s2 += t; t *= pp; s3 += t; }
        { float pp = pv.z, gg = gv.z; s0 += gg; float t = pp*gg; s1 += t; t *= pp; s2 += t; t *= pp; s3 += t; }
        { float pp = pv.w, gg = gv.w; s0 += gg; float t = pp*gg; s1 += t; t *= pp; s2 += t; t *= pp; s3 += t; }
    }
#pragma unroll
    for (int off = 16; off > 0; off >>= 1) {
        s0 += __shfl_down_sync(0xffffffffu, s0, off);
        s1 += __shfl_down_sync(0xffffffffu, s1, off);
        s2 += __shfl_down_sync(0xffffffffu, s2, off);
        s3 += __shfl_down_sync(0xffffffffu, s3, off);
    }
    __shared__ float red[4][32];
    int lane = threadIdx.x & 31, wid = threadIdx.x >> 5;
    if (lane == 0) { red[0][wid] = s0; red[1][wid] = s1; red[2][wid] = s2; red[3][wid] = s3; }
    __syncthreads();
    if (threadIdx.x == 0) {
        float S0 = 0.f, S1 = 0.f, S2 = 0.f, S3 = 0.f;
#pragma unroll
        for (int i = 0; i < 32; i++) { S0 += red[0][i]; S1 += red[1][i]; S2 += red[2][i]; S3 += red[3][i]; }
        const float tg   = 2.0f * 1e-4f;
        const float beta = expf(-tg);
        d_c[bg * 4 + 0] = beta * S0;
        d_c[bg * 4 + 1] = beta * tg * S1;
        d_c[bg * 4 + 2] = beta * (tg * tg * 0.5f) * S2;
        d_c[bg * 4 + 3] = beta * (tg * tg * tg * (1.f / 6.f)) * S3;
    }
}

// =====================================================================
// y = poly(t), z = Wz @ y (grouped, K=64) — f32x2 SIMT
// =====================================================================
__global__ void __launch_bounds__(256) k_yz(const float* __restrict__ Wz)
{
    extern __shared__ char sm3[];
    float*  Ys  = (float*)sm3;
    float2* Wzd = (float2*)(sm3 + 64 * 64 * 4);

    const int n0 = blockIdx.x * 64;
    const int g  = blockIdx.y;
    const int b  = blockIdx.z;
    const int tid = threadIdx.x;
    const int tx = tid & 15;
    const int ty = tid >> 4;

    const int cbase = (b * 8 + g) * 4;
    const float c0 = d_c[cbase + 0], c1 = d_c[cbase + 1];
    const float c2 = d_c[cbase + 2], c3 = d_c[cbase + 3];

    const float* Wzg = Wz + g * (128 * 64);
    for (int s = tid; s < 8192; s += 256) {
        float w = Wzg[s];
        Wzd[s] = make_float2(w, w);
    }
    const float* tb = d_t + ((size_t)b * P_ + g * 64) * HW_ + n0;
    for (int s = tid; s < 1024; s += 256) {
        int i  = s >> 4;
        int c4 = (s & 15) << 2;
        float4 tv = *(const float4*)&tb[(size_t)i * HW_ + c4];
        float4 yv;
        yv.x = ((c3 * tv.x + c2) * tv.x + c1) * tv.x + c0;
        yv.y = ((c3 * tv.y + c2) * tv.y + c1) * tv.y + c0;
        yv.z = ((c3 * tv.z + c2) * tv.z + c1) * tv.z + c0;
        yv.w = ((c3 * tv.w + c2) * tv.w + c1) * tv.w + c0;
        *(float4*)&Ys[i * 64 + c4] = yv;
    }
    __syncthreads();

    ull acc[8][2];
#pragma unroll
    for (int j = 0; j < 8; j++) { acc[j][0] = 0ULL; acc[j][1] = 0ULL; }

#pragma unroll 8
    for (int kk = 0; kk < 64; kk++) {
        ull xp0 = *(const ull*)&Ys[kk * 64 + tx * 4];
        ull xp1 = *(const ull*)&Ys[kk * 64 + tx * 4 + 2];
#pragma unroll
        for (int j = 0; j < 8; j++) {
            ull wd = *(const ull*)&Wzd[(ty * 8 + j) * 64 + kk];
            acc[j][0] = f2fma(wd, xp0, acc[j][0]);
            acc[j][1] = f2fma(wd, xp1, acc[j][1]);
        }
    }

    float* zb = d_z + ((size_t)b * C_ + g * 128) * HW_ + n0;
#pragma unroll
    for (int j = 0; j < 8; j++) {
        float4 v;
        f2unpack(acc[j][0], v.x, v.y);
        f2unpack(acc[j][1], v.z, v.w);
        *(float4*)&zb[(size_t)(ty * 8 + j) * HW_ + tx * 4] = v;
    }
}

// =====================================================================
// GroupNorm stats (1024 threads / block)
// =====================================================================
__global__ void __launch_bounds__(1024) k_gnstats()
{
    const int bg = blockIdx.x;
    const float4* z4 = (const float4*)(d_z + (size_t)bg * 131072);
    float s = 0.f, ss = 0.f;
    for (int i = threadIdx.x; i < 32768; i += 1024) {
        float4 v = z4[i];
        s  += (v.x + v.y) + (v.z + v.w);
        ss += v.x * v.x + v.y * v.y + v.z * v.z + v.w * v.w;
    }
#pragma unroll
    for (int off = 16; off > 0; off >>= 1) {
        s  += __shfl_down_sync(0xffffffffu, s, off);
        ss += __shfl_down_sync(0xffffffffu, ss, off);
    }
    __shared__ float red[2][32];
    int lane = threadIdx.x & 31, wid = threadIdx.x >> 5;
    if (lane == 0) { red[0][wid] = s; red[1][wid] = ss; }
    __syncthreads();
    if (threadIdx.x == 0) {
        float S = 0.f, SS = 0.f;
#pragma unroll
        for (int i = 0; i < 32; i++) { S += red[0][i]; SS += red[1][i]; }
        const float invN = 1.0f / 131072.0f;
        float mean = S * invN;
        float var  = SS * invN - mean * mean;
        d_stats[bg * 2 + 0] = mean;
        d_stats[bg * 2 + 1] = rsqrtf(var + 1e-5f);
    }
}

// =====================================================================
// finish: out = (z - mean)*rstd*gn_w + gn_b + x
// =====================================================================
__global__ void __launch_bounds__(256) k_finish(
    const float* __restrict__ x, const float* __restrict__ gn_w,
    const float* __restrict__ gn_b, float* __restrict__ out)
{
    int i4 = blockIdx.x * 256 + threadIdx.x;
    if (i4 >= (B_ * C_ * HW_) / 4) return;
    size_t idx = (size_t)i4 * 4;
    int ch = (int)((idx >> 10) & 1023);
    int b  = (int)(idx >> 20);
    int bg = b * 8 + (ch >> 7);
    float mean = d_stats[bg * 2 + 0];
    float rstd = d_stats[bg * 2 + 1];
    float a = gn_w[ch] * rstd;
    float c = gn_b[ch] - mean * a;
    float4 zv = *(const float4*)&d_z[idx];
    float4 xv = *(const float4*)&x[idx];
    float4 o;
    o.x = zv.x * a + c + xv.x;
    o.y = zv.y * a + c + xv.y;
    o.z = zv.z * a + c + xv.z;
    o.w = zv.w * a + c + xv.w;
    *(float4*)&out[idx] = o;
}

// =====================================================================
extern "C" void kernel_launch(void* const* d_in, const int* in_sizes, int n_in,
                              void* d_out, int out_size)
{
    const float* x   = (const float*)d_in[0];
    const float* Wt  = (const float*)d_in[1];
    const float* Wp  = (const float*)d_in[2];
    const float* Wg  = (const float*)d_in[3];
    const float* Wz  = (const float*)d_in[4];
    const float* gnw = (const float*)d_in[5];
    const float* gnb = (const float*)d_in[6];
    float* out = (float*)d_out;

    cudaFuncSetAttribute(k_gemm_mma, cudaFuncAttributeMaxDynamicSharedMemorySize, 2 * STG_B);
    cudaFuncSetAttribute(k_yz,       cudaFuncAttributeMaxDynamicSharedMemorySize, 81920);

    k_convW<<<dim3(512, 3), 256>>>(Wt, Wp, Wg);
    k_transX<<<dim3(32, 8, 16), 256>>>(x);

    dim3 gg(8, 4, 48);                 // ntile(128), mtile(128), b*3+w
    k_gemm_mma<<<gg, 256, 2 * STG_B>>>();

    k_att<<<B_ * G_, 1024>>>();

    dim3 g3(HW_ / 64, G_, B_);
    k_yz<<<g3, 256, 81920>>>(Wz);

    k_gnstats<<<B_ * G_, 1024>>>();

    int nblk5 = (B_ * C_ * HW_ / 4 + 255) / 256;
    k_finish<<<nblk5, 256>>>(x, gnw, gnb, out);
}

// round 5
// speedup vs baseline: 4.3592x; 1.6372x over previous
#include <cuda_runtime.h>
#include <cuda_bf16.h>
#include <cstdint>
#include <math.h>

typedef unsigned long long ull;

#define B_  16
#define C_  1024
#define P_  512
#define HW_ 1024
#define G_  8

// ---------------- scratch (static device globals; no allocation) ----------------
__device__ float d_t[(size_t)B_ * P_ * HW_];   // 32 MB
__device__ float d_z[(size_t)B_ * C_ * HW_];   // 64 MB
__device__ float d_S[B_ * G_ * 4];             // moment sums S_o per (b,g); S0 exact
__device__ float d_gn[B_ * G_ * 2];            // GN sum / sumsq per (b,g)
__device__ float d_xsum[B_ * C_];              // sum over spatial of x, per (b,c)
__device__ float d_wgsum[G_ * C_];             // sum over group rows of Wg, per (g,c)

// bf16 operands (hi only)
__device__ __nv_bfloat16 d_Whi[3u * 512u * 1024u];
__device__ __nv_bfloat16 d_XThi[(size_t)B_ * 1024u * 1024u];  // [b][n][k]

// ---------------- PTX helpers ----------------
__device__ __forceinline__ uint32_t smem_u32(const void* p) {
    uint32_t a;
    asm("{ .reg .u64 t; cvta.to.shared.u64 t, %1; cvt.u32.u64 %0, t; }" : "=r"(a) : "l"(p));
    return a;
}
#define CP_ASYNC16(sa, ga) \
    asm volatile("cp.async.cg.shared.global [%0], [%1], 16;" :: "r"(sa), "l"(ga))
#define CP_COMMIT()   asm volatile("cp.async.commit_group;" ::: "memory")
#define CP_WAIT(n)    asm volatile("cp.async.wait_group %0;" :: "n"(n) : "memory")

__device__ __forceinline__ void ldsm_x4(uint32_t& r0, uint32_t& r1, uint32_t& r2, uint32_t& r3,
                                        uint32_t addr) {
    asm volatile("ldmatrix.sync.aligned.m8n8.x4.shared.b16 {%0,%1,%2,%3}, [%4];"
                 : "=r"(r0), "=r"(r1), "=r"(r2), "=r"(r3) : "r"(addr));
}
__device__ __forceinline__ void mma16816(float* c, const uint32_t* a, uint32_t b0, uint32_t b1) {
    asm volatile("mma.sync.aligned.m16n8k16.row.col.f32.bf16.bf16.f32 "
                 "{%0,%1,%2,%3}, {%4,%5,%6,%7}, {%8,%9}, {%0,%1,%2,%3};"
                 : "+f"(c[0]), "+f"(c[1]), "+f"(c[2]), "+f"(c[3])
                 : "r"(a[0]), "r"(a[1]), "r"(a[2]), "r"(a[3]), "r"(b0), "r"(b1));
}

// packed f32x2 (for k_yz)
__device__ __forceinline__ ull f2fma(ull a, ull b, ull c) {
    ull d; asm("fma.rn.f32x2 %0, %1, %2, %3;" : "=l"(d) : "l"(a), "l"(b), "l"(c)); return d;
}
__device__ __forceinline__ void f2unpack(ull v, float& lo, float& hi) {
    asm("mov.b64 {%0, %1}, %2;" : "=f"(lo), "=f"(hi) : "l"(v));
}

// =====================================================================
// zero accumulators (must run every launch: graph-replay determinism)
// =====================================================================
__global__ void __launch_bounds__(256) k_zero()
{
    int i = blockIdx.x * 256 + threadIdx.x;
    if (i < B_ * C_) d_xsum[i] = 0.f;
    if (i < 512)     d_S[i]    = 0.f;
    if (i < 256)     d_gn[i]   = 0.f;
}

// =====================================================================
// Pre-pass A: W -> bf16 (hi only)
// =====================================================================
__global__ void __launch_bounds__(256) k_convW(
    const float* __restrict__ Wt, const float* __restrict__ Wp, const float* __restrict__ Wg)
{
    int w = blockIdx.y;
    const float* W = (w == 0) ? Wt : (w == 1) ? Wp : Wg;
    size_t idx = ((size_t)blockIdx.x * 256 + threadIdx.x) * 4;
    float4 v = *(const float4*)&W[idx];
    __nv_bfloat162 h01 = __floats2bfloat162_rn(v.x, v.y);
    __nv_bfloat162 h23 = __floats2bfloat162_rn(v.z, v.w);
    uint2 hv;
    hv.x = *(uint32_t*)&h01; hv.y = *(uint32_t*)&h23;
    *(uint2*)(d_Whi + (size_t)w * 524288u + idx) = hv;
}

// =====================================================================
// Pre-pass B: X [b][k][n] fp32 -> XT [b][n][k] bf16 (transpose),
// plus fp32 per-channel spatial sums (atomicAdd into d_xsum).
// =====================================================================
__global__ void __launch_bounds__(256) k_transX(const float* __restrict__ x)
{
    __shared__ float Xs[32][132];
    int k0 = blockIdx.x * 32;
    int n0 = blockIdx.y * 128;
    int b  = blockIdx.z;
    int tid = threadIdx.x;
    const float* xb = x + ((size_t)b * 1024 + k0) * 1024 + n0;
#pragma unroll
    for (int i = 0; i < 4; i++) {
        int slot = tid + i * 256;
        int r  = slot >> 5;
        int c4 = (slot & 31) * 4;
        *(float4*)&Xs[r][c4] = *(const float4*)&xb[(size_t)r * 1024 + c4];
    }
    __syncthreads();

    // exact fp32 channel sums over this 128-col window
    {
        int r = tid >> 3, q = tid & 7;
        float s = 0.f;
#pragma unroll
        for (int c = 0; c < 16; c++) s += Xs[r][q * 16 + c];
        s += __shfl_down_sync(0xffffffffu, s, 4);
        s += __shfl_down_sync(0xffffffffu, s, 2);
        s += __shfl_down_sync(0xffffffffu, s, 1);
        if (q == 0) atomicAdd(&d_xsum[b * 1024 + k0 + r], s);
    }

    int n  = tid >> 1;
    int kh = (tid & 1) * 16;
    uint32_t hi[8];
#pragma unroll
    for (int j = 0; j < 8; j++) {
        __nv_bfloat162 h = __floats2bfloat162_rn(Xs[kh + 2 * j][n], Xs[kh + 2 * j + 1][n]);
        hi[j] = *(uint32_t*)&h;
    }
    size_t off = ((size_t)b * 1024 + n0 + n) * 1024 + k0 + kh;
    *(uint4*)(d_XThi + off)     = make_uint4(hi[0], hi[1], hi[2], hi[3]);
    *(uint4*)(d_XThi + off + 8) = make_uint4(hi[4], hi[5], hi[6], hi[7]);
}

// =====================================================================
// Wg group-row sums: d_wgsum[g][c] = sum_{r in group g} Wg[g*64+r][c]  (fp32 exact)
// =====================================================================
__global__ void __launch_bounds__(1024) k_wgsum(const float* __restrict__ Wg)
{
    int g = blockIdx.x;
    int c = threadIdx.x;
    const float* base = Wg + (size_t)g * 64 * 1024 + c;
    float s = 0.f;
#pragma unroll 8
    for (int r = 0; r < 64; r++) s += base[(size_t)r * 1024];
    d_wgsum[g * 1024 + c] = s;
}

// =====================================================================
// Exact S0[b][g] = sum_c wgsum[g][c] * xsum[b][c]
// =====================================================================
__global__ void __launch_bounds__(256) k_s0()
{
    int bg = blockIdx.x;
    int b = bg >> 3, g = bg & 7;
    int tid = threadIdx.x;
    float s = 0.f;
    for (int c = tid; c < 1024; c += 256)
        s += d_wgsum[g * 1024 + c] * d_xsum[b * 1024 + c];
#pragma unroll
    for (int off = 16; off > 0; off >>= 1)
        s += __shfl_down_sync(0xffffffffu, s, off);
    __shared__ float red[8];
    if ((tid & 31) == 0) red[tid >> 5] = s;
    __syncthreads();
    if (tid == 0) {
        float S = 0.f;
#pragma unroll
        for (int i = 0; i < 8; i++) S += red[i];
        d_S[bg * 4 + 0] = S;     // exact S0 (direct write; slots 1..3 via atomics)
    }
}

// =====================================================================
// GEMM-T: t = Wt @ X.  CTA 128m x 128n, warp 64x32, single bf16 term.
// =====================================================================
#define NCH      32
#define ROWB     80
#define T_TILE_B 10240
#define T_STG    20480
#define T_OFF_A  0
#define T_OFF_B  10240

__device__ __forceinline__ void t_load_chunk(
    uint32_t sb, const __nv_bfloat16* gA, const __nv_bfloat16* gB, int k0, int tid)
{
#pragma unroll
    for (int i = 0; i < 4; i++) {
        int unit = tid + i * 256;
        int tile = unit >> 9;
        int rem  = unit & 511;
        int r = rem >> 2, u = rem & 3;
        uint32_t dst = sb + (uint32_t)tile * T_TILE_B + (uint32_t)r * ROWB + (uint32_t)u * 16;
        const __nv_bfloat16* src = (tile == 0 ? gA : gB) + (size_t)r * 1024 + k0 + u * 8;
        CP_ASYNC16(dst, (const void*)src);
    }
}

__global__ void __launch_bounds__(256, 2) k_gemm_t()
{
    extern __shared__ char smraw[];
    uint32_t sbase = smem_u32(smraw);

    const int tid  = threadIdx.x;
    const int wid  = tid >> 5;
    const int lane = tid & 31;
    const int wm   = wid & 1;
    const int wn   = wid >> 1;

    const int n0 = blockIdx.x * 128;
    const int m0 = blockIdx.y * 128;
    const int b  = blockIdx.z;

    const __nv_bfloat16* gA = d_Whi + (size_t)m0 * 1024;
    const __nv_bfloat16* gB = d_XThi + ((size_t)b * 1024 + n0) * 1024;

    float acc[4][4][4];
#pragma unroll
    for (int i = 0; i < 4; i++)
#pragma unroll
        for (int j = 0; j < 4; j++)
#pragma unroll
            for (int q = 0; q < 4; q++) acc[i][j][q] = 0.f;

    const uint32_t aLane = (uint32_t)((wm * 64 + (lane & 15)) * ROWB + (lane >> 4) * 16);
    const int bg = lane >> 3;
    const uint32_t bLane = (uint32_t)((wn * 32 + (bg >> 1) * 8 + (lane & 7)) * ROWB + (bg & 1) * 16);

    t_load_chunk(sbase, gA, gB, 0, tid);
    CP_COMMIT();

    for (int j = 0; j < NCH; j++) {
        const uint32_t sb = sbase + (uint32_t)(j & 1) * T_STG;
        if (j + 1 < NCH) {
            t_load_chunk(sbase + (uint32_t)((j + 1) & 1) * T_STG, gA, gB, (j + 1) * 32, tid);
            CP_COMMIT();
            CP_WAIT(1);
        } else {
            CP_WAIT(0);
        }
        __syncthreads();

#pragma unroll
        for (int s = 0; s < 2; s++) {
            const uint32_t kb = (uint32_t)s * 32;
            uint32_t A[4][4], Bv[4][2];
#pragma unroll
            for (int i = 0; i < 4; i++)
                ldsm_x4(A[i][0], A[i][1], A[i][2], A[i][3],
                        sb + T_OFF_A + aLane + (uint32_t)i * (16 * ROWB) + kb);
#pragma unroll
            for (int jp = 0; jp < 2; jp++)
                ldsm_x4(Bv[jp * 2][0], Bv[jp * 2][1], Bv[jp * 2 + 1][0], Bv[jp * 2 + 1][1],
                        sb + T_OFF_B + bLane + (uint32_t)jp * (16 * ROWB) + kb);
#pragma unroll
            for (int i = 0; i < 4; i++)
#pragma unroll
                for (int jj = 0; jj < 4; jj++)
                    mma16816(acc[i][jj], A[i], Bv[jj][0], Bv[jj][1]);
        }
        __syncthreads();
    }

    {
        const int rbase = m0 + wm * 64 + (lane >> 2);
        const int cbase = n0 + wn * 32 + (lane & 3) * 2;
        float* ob = d_t + (size_t)b * 512 * 1024;
#pragma unroll
        for (int i = 0; i < 4; i++) {
#pragma unroll
            for (int jj = 0; jj < 4; jj++) {
                size_t r0 = (size_t)(rbase + i * 16) * 1024 + cbase + jj * 8;
                *(float2*)(ob + r0)            = make_float2(acc[i][jj][0], acc[i][jj][1]);
                *(float2*)(ob + r0 + 8 * 1024) = make_float2(acc[i][jj][2], acc[i][jj][3]);
            }
        }
    }
}

// =====================================================================
// GEMM-PG: p and g tiles (dual accumulators); epilogue reduces moments
// S1..S3 = sum p^o g via atomicAdd (S0 comes from the exact path).
// CTA 128m x 64n, warps 4m x 2n (warp tile 32x32). p,g never hit DRAM.
// =====================================================================
#define PG_OFF_AP  0
#define PG_OFF_AG  10240
#define PG_OFF_B   20480
#define PG_STG     25600

__device__ __forceinline__ void pg_load_chunk(
    uint32_t sb, const __nv_bfloat16* gAp, const __nv_bfloat16* gAg,
    const __nv_bfloat16* gB, int k0, int tid)
{
#pragma unroll
    for (int i = 0; i < 5; i++) {
        int unit = tid + i * 256;
        const __nv_bfloat16* src;
        uint32_t dst;
        if (unit < 512) {
            int r = unit >> 2, u = unit & 3;
            dst = sb + PG_OFF_AP + (uint32_t)r * ROWB + (uint32_t)u * 16;
            src = gAp + (size_t)r * 1024 + k0 + u * 8;
        } else if (unit < 1024) {
            int rem = unit - 512;
            int r = rem >> 2, u = rem & 3;
            dst = sb + PG_OFF_AG + (uint32_t)r * ROWB + (uint32_t)u * 16;
            src = gAg + (size_t)r * 1024 + k0 + u * 8;
        } else {
            int rem = unit - 1024;
            int r = rem >> 2, u = rem & 3;
            dst = sb + PG_OFF_B + (uint32_t)r * ROWB + (uint32_t)u * 16;
            src = gB + (size_t)r * 1024 + k0 + u * 8;
        }
        CP_ASYNC16(dst, (const void*)src);
    }
}

__global__ void __launch_bounds__(256, 2) k_gemm_pg()
{
    extern __shared__ char smraw[];
    uint32_t sbase = smem_u32(smraw);

    const int tid  = threadIdx.x;
    const int wid  = tid >> 5;
    const int lane = tid & 31;
    const int wm   = wid & 3;
    const int wn   = wid >> 2;

    const int n0 = blockIdx.x * 64;
    const int m0 = blockIdx.y * 128;
    const int b  = blockIdx.z;

    const __nv_bfloat16* gAp = d_Whi + 1u * 524288u + (size_t)m0 * 1024;
    const __nv_bfloat16* gAg = d_Whi + 2u * 524288u + (size_t)m0 * 1024;
    const __nv_bfloat16* gB  = d_XThi + ((size_t)b * 1024 + n0) * 1024;

    float accp[2][4][4], accg[2][4][4];
#pragma unroll
    for (int i = 0; i < 2; i++)
#pragma unroll
        for (int j = 0; j < 4; j++)
#pragma unroll
            for (int q = 0; q < 4; q++) { accp[i][j][q] = 0.f; accg[i][j][q] = 0.f; }

    const uint32_t aLane = (uint32_t)((wm * 32 + (lane & 15)) * ROWB + (lane >> 4) * 16);
    const int bgrp = lane >> 3;
    const uint32_t bLane = (uint32_t)((wn * 32 + (bgrp >> 1) * 8 + (lane & 7)) * ROWB + (bgrp & 1) * 16);

    pg_load_chunk(sbase, gAp, gAg, gB, 0, tid);
    CP_COMMIT();

    for (int j = 0; j < NCH; j++) {
        const uint32_t sb = sbase + (uint32_t)(j & 1) * PG_STG;
        if (j + 1 < NCH) {
            pg_load_chunk(sbase + (uint32_t)((j + 1) & 1) * PG_STG, gAp, gAg, gB, (j + 1) * 32, tid);
            CP_COMMIT();
            CP_WAIT(1);
        } else {
            CP_WAIT(0);
        }
        __syncthreads();

#pragma unroll
        for (int s = 0; s < 2; s++) {
            const uint32_t kb = (uint32_t)s * 32;
            uint32_t Ap[2][4], Ag[2][4], Bv[4][2];
#pragma unroll
            for (int i = 0; i < 2; i++) {
                ldsm_x4(Ap[i][0], Ap[i][1], Ap[i][2], Ap[i][3],
                        sb + PG_OFF_AP + aLane + (uint32_t)i * (16 * ROWB) + kb);
                ldsm_x4(Ag[i][0], Ag[i][1], Ag[i][2], Ag[i][3],
                        sb + PG_OFF_AG + aLane + (uint32_t)i * (16 * ROWB) + kb);
            }
#pragma unroll
            for (int jp = 0; jp < 2; jp++)
                ldsm_x4(Bv[jp * 2][0], Bv[jp * 2][1], Bv[jp * 2 + 1][0], Bv[jp * 2 + 1][1],
                        sb + PG_OFF_B + bLane + (uint32_t)jp * (16 * ROWB) + kb);
#pragma unroll
            for (int i = 0; i < 2; i++)
#pragma unroll
                for (int jj = 0; jj < 4; jj++) {
                    mma16816(accp[i][jj], Ap[i], Bv[jj][0], Bv[jj][1]);
                    mma16816(accg[i][jj], Ag[i], Bv[jj][0], Bv[jj][1]);
                }
        }
        __syncthreads();
    }

    // moment epilogue (S1..S3 only; S0 exact elsewhere)
    {
        float s1 = 0.f, s2 = 0.f, s3 = 0.f;
#pragma unroll
        for (int i = 0; i < 2; i++)
#pragma unroll
            for (int jj = 0; jj < 4; jj++)
#pragma unroll
                for (int q = 0; q < 4; q++) {
                    float pv = accp[i][jj][q];
                    float gv = accg[i][jj][q];
                    float t1 = pv * gv; s1 += t1;
                    t1 *= pv; s2 += t1;
                    t1 *= pv; s3 += t1;
                }
#pragma unroll
        for (int off = 16; off > 0; off >>= 1) {
            s1 += __shfl_down_sync(0xffffffffu, s1, off);
            s2 += __shfl_down_sync(0xffffffffu, s2, off);
            s3 += __shfl_down_sync(0xffffffffu, s3, off);
        }
        if (lane == 0) {
            int g = (m0 >> 6) + (wm >> 1);
            float* Sp = d_S + (b * 8 + g) * 4;
            atomicAdd(Sp + 1, s1);
            atomicAdd(Sp + 2, s2);
            atomicAdd(Sp + 3, s3);
        }
    }
}

// =====================================================================
// y = poly(t) with c_o = beta*(2g)^o/o! * S_o, z = Wz @ y (K=64),
// plus inline GroupNorm partial sums.
// =====================================================================
__global__ void __launch_bounds__(256) k_yz(const float* __restrict__ Wz)
{
    extern __shared__ char sm3[];
    float*  Ys  = (float*)sm3;
    float2* Wzd = (float2*)(sm3 + 64 * 64 * 4);

    const int n0 = blockIdx.x * 64;
    const int g  = blockIdx.y;
    const int b  = blockIdx.z;
    const int tid = threadIdx.x;
    const int tx = tid & 15;
    const int ty = tid >> 4;
    const int bgidx = b * 8 + g;

    const float tg   = 2.0f * 1e-4f;
    const float beta = expf(-tg);
    const float c0 = beta * d_S[bgidx * 4 + 0];
    const float c1 = beta * tg * d_S[bgidx * 4 + 1];
    const float c2 = beta * (tg * tg * 0.5f) * d_S[bgidx * 4 + 2];
    const float c3 = beta * (tg * tg * tg * (1.f / 6.f)) * d_S[bgidx * 4 + 3];

    const float* Wzg = Wz + g * (128 * 64);
    for (int s = tid; s < 8192; s += 256) {
        float w = Wzg[s];
        Wzd[s] = make_float2(w, w);
    }
    const float* tb = d_t + ((size_t)b * P_ + g * 64) * HW_ + n0;
    for (int s = tid; s < 1024; s += 256) {
        int i  = s >> 4;
        int c4 = (s & 15) << 2;
        float4 tv = *(const float4*)&tb[(size_t)i * HW_ + c4];
        float4 yv;
        yv.x = ((c3 * tv.x + c2) * tv.x + c1) * tv.x + c0;
        yv.y = ((c3 * tv.y + c2) * tv.y + c1) * tv.y + c0;
        yv.z = ((c3 * tv.z + c2) * tv.z + c1) * tv.z + c0;
        yv.w = ((c3 * tv.w + c2) * tv.w + c1) * tv.w + c0;
        *(float4*)&Ys[i * 64 + c4] = yv;
    }
    __syncthreads();

    ull acc[8][2];
#pragma unroll
    for (int j = 0; j < 8; j++) { acc[j][0] = 0ULL; acc[j][1] = 0ULL; }

#pragma unroll 8
    for (int kk = 0; kk < 64; kk++) {
        ull xp0 = *(const ull*)&Ys[kk * 64 + tx * 4];
        ull xp1 = *(const ull*)&Ys[kk * 64 + tx * 4 + 2];
#pragma unroll
        for (int j = 0; j < 8; j++) {
            ull wd = *(const ull*)&Wzd[(ty * 8 + j) * 64 + kk];
            acc[j][0] = f2fma(wd, xp0, acc[j][0]);
            acc[j][1] = f2fma(wd, xp1, acc[j][1]);
        }
    }

    float* zb = d_z + ((size_t)b * C_ + g * 128) * HW_ + n0;
    float ls = 0.f, lss = 0.f;
#pragma unroll
    for (int j = 0; j < 8; j++) {
        float4 v;
        f2unpack(acc[j][0], v.x, v.y);
        f2unpack(acc[j][1], v.z, v.w);
        *(float4*)&zb[(size_t)(ty * 8 + j) * HW_ + tx * 4] = v;
        ls  += (v.x + v.y) + (v.z + v.w);
        lss += v.x * v.x + v.y * v.y + v.z * v.z + v.w * v.w;
    }
#pragma unroll
    for (int off = 16; off > 0; off >>= 1) {
        ls  += __shfl_down_sync(0xffffffffu, ls, off);
        lss += __shfl_down_sync(0xffffffffu, lss, off);
    }
    __shared__ float red[2][8];
    int lane = tid & 31, wrp = tid >> 5;
    if (lane == 0) { red[0][wrp] = ls; red[1][wrp] = lss; }
    __syncthreads();
    if (tid == 0) {
        float S = 0.f, SS = 0.f;
#pragma unroll
        for (int i = 0; i < 8; i++) { S += red[0][i]; SS += red[1][i]; }
        atomicAdd(&d_gn[bgidx * 2 + 0], S);
        atomicAdd(&d_gn[bgidx * 2 + 1], SS);
    }
}

// =====================================================================
// finish: out = (z - mean)*rstd*gn_w + gn_b + x
// =====================================================================
__global__ void __launch_bounds__(256) k_finish(
    const float* __restrict__ x, const float* __restrict__ gn_w,
    const float* __restrict__ gn_b, float* __restrict__ out)
{
    int i4 = blockIdx.x * 256 + threadIdx.x;
    if (i4 >= (B_ * C_ * HW_) / 4) return;
    size_t idx = (size_t)i4 * 4;
    int ch = (int)((idx >> 10) & 1023);
    int b  = (int)(idx >> 20);
    int bg = b * 8 + (ch >> 7);
    const float invN = 1.0f / 131072.0f;
    float s  = d_gn[bg * 2 + 0];
    float ss = d_gn[bg * 2 + 1];
    float mean = s * invN;
    float var  = ss * invN - mean * mean;
    float rstd = rsqrtf(var + 1e-5f);
    float a = gn_w[ch] * rstd;
    float c = gn_b[ch] - mean * a;
    float4 zv = *(const float4*)&d_z[idx];
    float4 xv = *(const float4*)&x[idx];
    float4 o;
    o.x = zv.x * a + c + xv.x;
    o.y = zv.y * a + c + xv.y;
    o.z = zv.z * a + c + xv.z;
    o.w = zv.w * a + c + xv.w;
    *(float4*)&out[idx] = o;
}

// =====================================================================
extern "C" void kernel_launch(void* const* d_in, const int* in_sizes, int n_in,
                              void* d_out, int out_size)
{
    const float* x   = (const float*)d_in[0];
    const float* Wt  = (const float*)d_in[1];
    const float* Wp  = (const float*)d_in[2];
    const float* Wg  = (const float*)d_in[3];
    const float* Wz  = (const float*)d_in[4];
    const float* gnw = (const float*)d_in[5];
    const float* gnb = (const float*)d_in[6];
    float* out = (float*)d_out;

    cudaFuncSetAttribute(k_gemm_t,  cudaFuncAttributeMaxDynamicSharedMemorySize, 2 * T_STG);
    cudaFuncSetAttribute(k_gemm_pg, cudaFuncAttributeMaxDynamicSharedMemorySize, 2 * PG_STG);
    cudaFuncSetAttribute(k_yz,      cudaFuncAttributeMaxDynamicSharedMemorySize, 81920);

    k_zero<<<64, 256>>>();
    k_convW<<<dim3(512, 3), 256>>>(Wt, Wp, Wg);
    k_transX<<<dim3(32, 8, 16), 256>>>(x);
    k_wgsum<<<8, 1024>>>(Wg);
    k_s0<<<128, 256>>>();

    k_gemm_t<<<dim3(8, 4, 16), 256, 2 * T_STG>>>();
    k_gemm_pg<<<dim3(16, 4, 16), 256, 2 * PG_STG>>>();

    dim3 g3(HW_ / 64, G_, B_);
    k_yz<<<g3, 256, 81920>>>(Wz);

    int nblk5 = (B_ * C_ * HW_ / 4 + 255) / 256;
    k_finish<<<nblk5, 256>>>(x, gnw, gnb, out);
}

// round 6
// speedup vs baseline: 4.4904x; 1.0301x over previous
#include <cuda_runtime.h>
#include <cuda_bf16.h>
#include <cstdint>
#include <math.h>

typedef unsigned long long ull;

#define B_  16
#define C_  1024
#define P_  512
#define HW_ 1024
#define G_  8

// ---------------- scratch (static device globals; no allocation) ----------------
__device__ __nv_bfloat16 d_t[(size_t)B_ * P_ * HW_];   // 16 MB (bf16 now)
__device__ float d_z[(size_t)B_ * C_ * HW_];           // 64 MB
__device__ float d_S[B_ * G_ * 4];                     // moment sums; S0 exact
__device__ float d_gn[B_ * G_ * 2];                    // GN sum / sumsq
__device__ float d_xsum[B_ * C_];                      // per (b,c) spatial sums
__device__ float d_wgsum[G_ * C_];                     // per (g,c) Wg row sums

// bf16 operands (hi only)
__device__ __nv_bfloat16 d_Whi[3u * 512u * 1024u];
__device__ __nv_bfloat16 d_XThi[(size_t)B_ * 1024u * 1024u];  // [b][n][k]

// ---------------- PTX helpers ----------------
__device__ __forceinline__ uint32_t smem_u32(const void* p) {
    uint32_t a;
    asm("{ .reg .u64 t; cvta.to.shared.u64 t, %1; cvt.u32.u64 %0, t; }" : "=r"(a) : "l"(p));
    return a;
}
#define CP_ASYNC16(sa, ga) \
    asm volatile("cp.async.cg.shared.global [%0], [%1], 16;" :: "r"(sa), "l"(ga))
#define CP_COMMIT()   asm volatile("cp.async.commit_group;" ::: "memory")
#define CP_WAIT(n)    asm volatile("cp.async.wait_group %0;" :: "n"(n) : "memory")

__device__ __forceinline__ void ldsm_x4(uint32_t& r0, uint32_t& r1, uint32_t& r2, uint32_t& r3,
                                        uint32_t addr) {
    asm volatile("ldmatrix.sync.aligned.m8n8.x4.shared.b16 {%0,%1,%2,%3}, [%4];"
                 : "=r"(r0), "=r"(r1), "=r"(r2), "=r"(r3) : "r"(addr));
}
__device__ __forceinline__ void mma16816(float* c, const uint32_t* a, uint32_t b0, uint32_t b1) {
    asm volatile("mma.sync.aligned.m16n8k16.row.col.f32.bf16.bf16.f32 "
                 "{%0,%1,%2,%3}, {%4,%5,%6,%7}, {%8,%9}, {%0,%1,%2,%3};"
                 : "+f"(c[0]), "+f"(c[1]), "+f"(c[2]), "+f"(c[3])
                 : "r"(a[0]), "r"(a[1]), "r"(a[2]), "r"(a[3]), "r"(b0), "r"(b1));
}

// packed f32x2 (for k_yz)
__device__ __forceinline__ ull f2fma(ull a, ull b, ull c) {
    ull d; asm("fma.rn.f32x2 %0, %1, %2, %3;" : "=l"(d) : "l"(a), "l"(b), "l"(c)); return d;
}
__device__ __forceinline__ void f2unpack(ull v, float& lo, float& hi) {
    asm("mov.b64 {%0, %1}, %2;" : "=f"(lo), "=f"(hi) : "l"(v));
}

// =====================================================================
// zero accumulators (every launch: graph-replay determinism)
// =====================================================================
__global__ void __launch_bounds__(256) k_zero()
{
    int i = blockIdx.x * 256 + threadIdx.x;
    if (i < B_ * C_)  d_xsum[i]  = 0.f;
    if (i < G_ * C_)  d_wgsum[i] = 0.f;
    if (i < 512)      d_S[i]     = 0.f;
    if (i < 256)      d_gn[i]    = 0.f;
}

// =====================================================================
// W -> bf16
// =====================================================================
__global__ void __launch_bounds__(256) k_convW(
    const float* __restrict__ Wt, const float* __restrict__ Wp, const float* __restrict__ Wg)
{
    int w = blockIdx.y;
    const float* W = (w == 0) ? Wt : (w == 1) ? Wp : Wg;
    size_t idx = ((size_t)blockIdx.x * 256 + threadIdx.x) * 4;
    float4 v = *(const float4*)&W[idx];
    __nv_bfloat162 h01 = __floats2bfloat162_rn(v.x, v.y);
    __nv_bfloat162 h23 = __floats2bfloat162_rn(v.z, v.w);
    uint2 hv;
    hv.x = *(uint32_t*)&h01; hv.y = *(uint32_t*)&h23;
    *(uint2*)(d_Whi + (size_t)w * 524288u + idx) = hv;
}

// =====================================================================
// X transpose + split to bf16, + exact fp32 channel sums
// =====================================================================
__global__ void __launch_bounds__(256) k_transX(const float* __restrict__ x)
{
    __shared__ float Xs[32][132];
    int k0 = blockIdx.x * 32;
    int n0 = blockIdx.y * 128;
    int b  = blockIdx.z;
    int tid = threadIdx.x;
    const float* xb = x + ((size_t)b * 1024 + k0) * 1024 + n0;
#pragma unroll
    for (int i = 0; i < 4; i++) {
        int slot = tid + i * 256;
        int r  = slot >> 5;
        int c4 = (slot & 31) * 4;
        *(float4*)&Xs[r][c4] = *(const float4*)&xb[(size_t)r * 1024 + c4];
    }
    __syncthreads();

    {
        int r = tid >> 3, q = tid & 7;
        float s = 0.f;
#pragma unroll
        for (int c = 0; c < 16; c++) s += Xs[r][q * 16 + c];
        s += __shfl_down_sync(0xffffffffu, s, 4);
        s += __shfl_down_sync(0xffffffffu, s, 2);
        s += __shfl_down_sync(0xffffffffu, s, 1);
        if (q == 0) atomicAdd(&d_xsum[b * 1024 + k0 + r], s);
    }

    int n  = tid >> 1;
    int kh = (tid & 1) * 16;
    uint32_t hi[8];
#pragma unroll
    for (int j = 0; j < 8; j++) {
        __nv_bfloat162 h = __floats2bfloat162_rn(Xs[kh + 2 * j][n], Xs[kh + 2 * j + 1][n]);
        hi[j] = *(uint32_t*)&h;
    }
    size_t off = ((size_t)b * 1024 + n0 + n) * 1024 + k0 + kh;
    *(uint4*)(d_XThi + off)     = make_uint4(hi[0], hi[1], hi[2], hi[3]);
    *(uint4*)(d_XThi + off + 8) = make_uint4(hi[4], hi[5], hi[6], hi[7]);
}

// =====================================================================
// Wg group-row sums (parallel over 64 blocks)
// =====================================================================
__global__ void __launch_bounds__(1024) k_wgsum(const float* __restrict__ Wg)
{
    int g  = blockIdx.x;
    int rc = blockIdx.y;          // 8 row-chunks of 8
    int c  = threadIdx.x;
    const float* base = Wg + ((size_t)g * 64 + rc * 8) * 1024 + c;
    float s = 0.f;
#pragma unroll
    for (int r = 0; r < 8; r++) s += base[(size_t)r * 1024];
    atomicAdd(&d_wgsum[g * 1024 + c], s);
}

// =====================================================================
// Exact S0[b][g] = sum_c wgsum[g][c] * xsum[b][c]
// =====================================================================
__global__ void __launch_bounds__(256) k_s0()
{
    int bg = blockIdx.x;
    int b = bg >> 3, g = bg & 7;
    int tid = threadIdx.x;
    float s = 0.f;
    for (int c = tid; c < 1024; c += 256)
        s += d_wgsum[g * 1024 + c] * d_xsum[b * 1024 + c];
#pragma unroll
    for (int off = 16; off > 0; off >>= 1)
        s += __shfl_down_sync(0xffffffffu, s, off);
    __shared__ float red[8];
    if ((tid & 31) == 0) red[tid >> 5] = s;
    __syncthreads();
    if (tid == 0) {
        float S = 0.f;
#pragma unroll
        for (int i = 0; i < 8; i++) S += red[i];
        d_S[bg * 4 + 0] = S;
    }
}

// =====================================================================
// GEMM-T: t = Wt @ X.  CTA 128x128, 8 warps (64x32), bf16 out.
// =====================================================================
#define NCH      32
#define ROWB     80
#define T_TILE_B 10240
#define T_STG    20480
#define T_OFF_A  0
#define T_OFF_B  10240

__device__ __forceinline__ void t_load_chunk(
    uint32_t sb, const __nv_bfloat16* gA, const __nv_bfloat16* gB, int k0, int tid)
{
#pragma unroll
    for (int i = 0; i < 4; i++) {
        int unit = tid + i * 256;
        int tile = unit >> 9;
        int rem  = unit & 511;
        int r = rem >> 2, u = rem & 3;
        uint32_t dst = sb + (uint32_t)tile * T_TILE_B + (uint32_t)r * ROWB + (uint32_t)u * 16;
        const __nv_bfloat16* src = (tile == 0 ? gA : gB) + (size_t)r * 1024 + k0 + u * 8;
        CP_ASYNC16(dst, (const void*)src);
    }
}

__global__ void __launch_bounds__(256, 2) k_gemm_t()
{
    extern __shared__ char smraw[];
    uint32_t sbase = smem_u32(smraw);

    const int tid  = threadIdx.x;
    const int wid  = tid >> 5;
    const int lane = tid & 31;
    const int wm   = wid & 1;
    const int wn   = wid >> 1;

    const int n0 = blockIdx.x * 128;
    const int m0 = blockIdx.y * 128;
    const int b  = blockIdx.z;

    const __nv_bfloat16* gA = d_Whi + (size_t)m0 * 1024;
    const __nv_bfloat16* gB = d_XThi + ((size_t)b * 1024 + n0) * 1024;

    float acc[4][4][4];
#pragma unroll
    for (int i = 0; i < 4; i++)
#pragma unroll
        for (int j = 0; j < 4; j++)
#pragma unroll
            for (int q = 0; q < 4; q++) acc[i][j][q] = 0.f;

    const uint32_t aLane = (uint32_t)((wm * 64 + (lane & 15)) * ROWB + (lane >> 4) * 16);
    const int bg = lane >> 3;
    const uint32_t bLane = (uint32_t)((wn * 32 + (bg >> 1) * 8 + (lane & 7)) * ROWB + (bg & 1) * 16);

    t_load_chunk(sbase, gA, gB, 0, tid);
    CP_COMMIT();

    for (int j = 0; j < NCH; j++) {
        const uint32_t sb = sbase + (uint32_t)(j & 1) * T_STG;
        if (j + 1 < NCH) {
            t_load_chunk(sbase + (uint32_t)((j + 1) & 1) * T_STG, gA, gB, (j + 1) * 32, tid);
            CP_COMMIT();
            CP_WAIT(1);
        } else {
            CP_WAIT(0);
        }
        __syncthreads();

#pragma unroll
        for (int s = 0; s < 2; s++) {
            const uint32_t kb = (uint32_t)s * 32;
            uint32_t A[4][4], Bv[4][2];
#pragma unroll
            for (int i = 0; i < 4; i++)
                ldsm_x4(A[i][0], A[i][1], A[i][2], A[i][3],
                        sb + T_OFF_A + aLane + (uint32_t)i * (16 * ROWB) + kb);
#pragma unroll
            for (int jp = 0; jp < 2; jp++)
                ldsm_x4(Bv[jp * 2][0], Bv[jp * 2][1], Bv[jp * 2 + 1][0], Bv[jp * 2 + 1][1],
                        sb + T_OFF_B + bLane + (uint32_t)jp * (16 * ROWB) + kb);
#pragma unroll
            for (int i = 0; i < 4; i++)
#pragma unroll
                for (int jj = 0; jj < 4; jj++)
                    mma16816(acc[i][jj], A[i], Bv[jj][0], Bv[jj][1]);
        }
        __syncthreads();
    }

    // epilogue -> bf16
    {
        const int rbase = m0 + wm * 64 + (lane >> 2);
        const int cbase = n0 + wn * 32 + (lane & 3) * 2;
        __nv_bfloat16* ob = d_t + (size_t)b * 512 * 1024;
#pragma unroll
        for (int i = 0; i < 4; i++) {
#pragma unroll
            for (int jj = 0; jj < 4; jj++) {
                size_t r0 = (size_t)(rbase + i * 16) * 1024 + cbase + jj * 8;
                __nv_bfloat162 v0 = __floats2bfloat162_rn(acc[i][jj][0], acc[i][jj][1]);
                __nv_bfloat162 v1 = __floats2bfloat162_rn(acc[i][jj][2], acc[i][jj][3]);
                *(uint32_t*)(ob + r0)            = *(uint32_t*)&v0;
                *(uint32_t*)(ob + r0 + 8 * 1024) = *(uint32_t*)&v1;
            }
        }
    }
}

// =====================================================================
// GEMM-PG: CTA 128m x 128n, 512 threads / 16 warps (warp 32x32), dual
// p/g accumulators; epilogue reduces S1..S3 via atomicAdd. p,g stay on-chip.
// =====================================================================
#define PG_OFF_AP  0
#define PG_OFF_AG  10240
#define PG_OFF_B   20480
#define PG_STG     30720

__device__ __forceinline__ void pg_load_chunk(
    uint32_t sb, const __nv_bfloat16* gAp, const __nv_bfloat16* gAg,
    const __nv_bfloat16* gB, int k0, int tid)
{
    const __nv_bfloat16* srcs[3] = {gAp, gAg, gB};
#pragma unroll
    for (int i = 0; i < 3; i++) {
        int r = tid >> 2, u = tid & 3;
        uint32_t dst = sb + (uint32_t)i * T_TILE_B + (uint32_t)r * ROWB + (uint32_t)u * 16;
        CP_ASYNC16(dst, (const void*)(srcs[i] + (size_t)r * 1024 + k0 + u * 8));
    }
}

__global__ void __launch_bounds__(512, 1) k_gemm_pg()
{
    extern __shared__ char smraw[];
    uint32_t sbase = smem_u32(smraw);

    const int tid  = threadIdx.x;
    const int wid  = tid >> 5;
    const int lane = tid & 31;
    const int wm   = wid & 3;       // 4 m-subtiles of 32
    const int wn   = wid >> 2;      // 4 n-subtiles of 32

    const int n0 = blockIdx.x * 128;
    const int m0 = blockIdx.y * 128;
    const int b  = blockIdx.z;

    const __nv_bfloat16* gAp = d_Whi + 1u * 524288u + (size_t)m0 * 1024;
    const __nv_bfloat16* gAg = d_Whi + 2u * 524288u + (size_t)m0 * 1024;
    const __nv_bfloat16* gB  = d_XThi + ((size_t)b * 1024 + n0) * 1024;

    float accp[2][4][4], accg[2][4][4];
#pragma unroll
    for (int i = 0; i < 2; i++)
#pragma unroll
        for (int j = 0; j < 4; j++)
#pragma unroll
            for (int q = 0; q < 4; q++) { accp[i][j][q] = 0.f; accg[i][j][q] = 0.f; }

    const uint32_t aLane = (uint32_t)((wm * 32 + (lane & 15)) * ROWB + (lane >> 4) * 16);
    const int bgrp = lane >> 3;
    const uint32_t bLane = (uint32_t)((wn * 32 + (bgrp >> 1) * 8 + (lane & 7)) * ROWB + (bgrp & 1) * 16);

    pg_load_chunk(sbase, gAp, gAg, gB, 0, tid);
    CP_COMMIT();

    for (int j = 0; j < NCH; j++) {
        const uint32_t sb = sbase + (uint32_t)(j & 1) * PG_STG;
        if (j + 1 < NCH) {
            pg_load_chunk(sbase + (uint32_t)((j + 1) & 1) * PG_STG, gAp, gAg, gB, (j + 1) * 32, tid);
            CP_COMMIT();
            CP_WAIT(1);
        } else {
            CP_WAIT(0);
        }
        __syncthreads();

#pragma unroll
        for (int s = 0; s < 2; s++) {
            const uint32_t kb = (uint32_t)s * 32;
            uint32_t Ap[2][4], Ag[2][4], Bv[4][2];
#pragma unroll
            for (int i = 0; i < 2; i++) {
                ldsm_x4(Ap[i][0], Ap[i][1], Ap[i][2], Ap[i][3],
                        sb + PG_OFF_AP + aLane + (uint32_t)i * (16 * ROWB) + kb);
                ldsm_x4(Ag[i][0], Ag[i][1], Ag[i][2], Ag[i][3],
                        sb + PG_OFF_AG + aLane + (uint32_t)i * (16 * ROWB) + kb);
            }
#pragma unroll
            for (int jp = 0; jp < 2; jp++)
                ldsm_x4(Bv[jp * 2][0], Bv[jp * 2][1], Bv[jp * 2 + 1][0], Bv[jp * 2 + 1][1],
                        sb + PG_OFF_B + bLane + (uint32_t)jp * (16 * ROWB) + kb);
#pragma unroll
            for (int i = 0; i < 2; i++)
#pragma unroll
                for (int jj = 0; jj < 4; jj++) {
                    mma16816(accp[i][jj], Ap[i], Bv[jj][0], Bv[jj][1]);
                    mma16816(accg[i][jj], Ag[i], Bv[jj][0], Bv[jj][1]);
                }
        }
        __syncthreads();
    }

    // moment epilogue (S1..S3; S0 exact elsewhere). Warp spans 32 m-rows in one group.
    {
        float s1 = 0.f, s2 = 0.f, s3 = 0.f;
#pragma unroll
        for (int i = 0; i < 2; i++)
#pragma unroll
            for (int jj = 0; jj < 4; jj++)
#pragma unroll
                for (int q = 0; q < 4; q++) {
                    float pv = accp[i][jj][q];
                    float gv = accg[i][jj][q];
                    float t1 = pv * gv; s1 += t1;
                    t1 *= pv; s2 += t1;
                    t1 *= pv; s3 += t1;
                }
#pragma unroll
        for (int off = 16; off > 0; off >>= 1) {
            s1 += __shfl_down_sync(0xffffffffu, s1, off);
            s2 += __shfl_down_sync(0xffffffffu, s2, off);
            s3 += __shfl_down_sync(0xffffffffu, s3, off);
        }
        if (lane == 0) {
            int g = (m0 >> 6) + (wm >> 1);
            float* Sp = d_S + (b * 8 + g) * 4;
            atomicAdd(Sp + 1, s1);
            atomicAdd(Sp + 2, s2);
            atomicAdd(Sp + 3, s3);
        }
    }
}

// =====================================================================
// y = poly(t), z = Wz @ y (K=64), + inline GroupNorm partial sums.
// =====================================================================
__global__ void __launch_bounds__(256) k_yz(const float* __restrict__ Wz)
{
    extern __shared__ char sm3[];
    float*  Ys  = (float*)sm3;
    float2* Wzd = (float2*)(sm3 + 64 * 64 * 4);

    const int n0 = blockIdx.x * 64;
    const int g  = blockIdx.y;
    const int b  = blockIdx.z;
    const int tid = threadIdx.x;
    const int tx = tid & 15;
    const int ty = tid >> 4;
    const int bgidx = b * 8 + g;

    const float tg   = 2.0f * 1e-4f;
    const float beta = expf(-tg);
    const float c0 = beta * d_S[bgidx * 4 + 0];
    const float c1 = beta * tg * d_S[bgidx * 4 + 1];
    const float c2 = beta * (tg * tg * 0.5f) * d_S[bgidx * 4 + 2];
    const float c3 = beta * (tg * tg * tg * (1.f / 6.f)) * d_S[bgidx * 4 + 3];

    const float* Wzg = Wz + g * (128 * 64);
    for (int s = tid; s < 8192; s += 256) {
        float w = Wzg[s];
        Wzd[s] = make_float2(w, w);
    }
    const __nv_bfloat16* tb = d_t + ((size_t)b * P_ + g * 64) * HW_ + n0;
    for (int s = tid; s < 1024; s += 256) {
        int i  = s >> 4;
        int c4 = (s & 15) << 2;
        uint2 raw = *(const uint2*)&tb[(size_t)i * HW_ + c4];
        __nv_bfloat162 t01 = *(__nv_bfloat162*)&raw.x;
        __nv_bfloat162 t23 = *(__nv_bfloat162*)&raw.y;
        float4 tv;
        tv.x = __low2float(t01); tv.y = __high2float(t01);
        tv.z = __low2float(t23); tv.w = __high2float(t23);
        float4 yv;
        yv.x = ((c3 * tv.x + c2) * tv.x + c1) * tv.x + c0;
        yv.y = ((c3 * tv.y + c2) * tv.y + c1) * tv.y + c0;
        yv.z = ((c3 * tv.z + c2) * tv.z + c1) * tv.z + c0;
        yv.w = ((c3 * tv.w + c2) * tv.w + c1) * tv.w + c0;
        *(float4*)&Ys[i * 64 + c4] = yv;
    }
    __syncthreads();

    ull acc[8][2];
#pragma unroll
    for (int j = 0; j < 8; j++) { acc[j][0] = 0ULL; acc[j][1] = 0ULL; }

#pragma unroll 8
    for (int kk = 0; kk < 64; kk++) {
        ull xp0 = *(const ull*)&Ys[kk * 64 + tx * 4];
        ull xp1 = *(const ull*)&Ys[kk * 64 + tx * 4 + 2];
#pragma unroll
        for (int j = 0; j < 8; j++) {
            ull wd = *(const ull*)&Wzd[(ty * 8 + j) * 64 + kk];
            acc[j][0] = f2fma(wd, xp0, acc[j][0]);
            acc[j][1] = f2fma(wd, xp1, acc[j][1]);
        }
    }

    float* zb = d_z + ((size_t)b * C_ + g * 128) * HW_ + n0;
    float ls = 0.f, lss = 0.f;
#pragma unroll
    for (int j = 0; j < 8; j++) {
        float4 v;
        f2unpack(acc[j][0], v.x, v.y);
        f2unpack(acc[j][1], v.z, v.w);
        *(float4*)&zb[(size_t)(ty * 8 + j) * HW_ + tx * 4] = v;
        ls  += (v.x + v.y) + (v.z + v.w);
        lss += v.x * v.x + v.y * v.y + v.z * v.z + v.w * v.w;
    }
#pragma unroll
    for (int off = 16; off > 0; off >>= 1) {
        ls  += __shfl_down_sync(0xffffffffu, ls, off);
        lss += __shfl_down_sync(0xffffffffu, lss, off);
    }
    __shared__ float red[2][8];
    int lane = tid & 31, wrp = tid >> 5;
    if (lane == 0) { red[0][wrp] = ls; red[1][wrp] = lss; }
    __syncthreads();
    if (tid == 0) {
        float S = 0.f, SS = 0.f;
#pragma unroll
        for (int i = 0; i < 8; i++) { S += red[0][i]; SS += red[1][i]; }
        atomicAdd(&d_gn[bgidx * 2 + 0], S);
        atomicAdd(&d_gn[bgidx * 2 + 1], SS);
    }
}

// =====================================================================
// finish: out = (z - mean)*rstd*gn_w + gn_b + x
// =====================================================================
__global__ void __launch_bounds__(256) k_finish(
    const float* __restrict__ x, const float* __restrict__ gn_w,
    const float* __restrict__ gn_b, float* __restrict__ out)
{
    int i4 = blockIdx.x * 256 + threadIdx.x;
    if (i4 >= (B_ * C_ * HW_) / 4) return;
    size_t idx = (size_t)i4 * 4;
    int ch = (int)((idx >> 10) & 1023);
    int b  = (int)(idx >> 20);
    int bg = b * 8 + (ch >> 7);
    const float invN = 1.0f / 131072.0f;
    float s  = d_gn[bg * 2 + 0];
    float ss = d_gn[bg * 2 + 1];
    float mean = s * invN;
    float var  = ss * invN - mean * mean;
    float rstd = rsqrtf(var + 1e-5f);
    float a = gn_w[ch] * rstd;
    float c = gn_b[ch] - mean * a;
    float4 zv = *(const float4*)&d_z[idx];
    float4 xv = *(const float4*)&x[idx];
    float4 o;
    o.x = zv.x * a + c + xv.x;
    o.y = zv.y * a + c + xv.y;
    o.z = zv.z * a + c + xv.z;
    o.w = zv.w * a + c + xv.w;
    *(float4*)&out[idx] = o;
}

// =====================================================================
extern "C" void kernel_launch(void* const* d_in, const int* in_sizes, int n_in,
                              void* d_out, int out_size)
{
    const float* x   = (const float*)d_in[0];
    const float* Wt  = (const float*)d_in[1];
    const float* Wp  = (const float*)d_in[2];
    const float* Wg  = (const float*)d_in[3];
    const float* Wz  = (const float*)d_in[4];
    const float* gnw = (const float*)d_in[5];
    const float* gnb = (const float*)d_in[6];
    float* out = (float*)d_out;

    cudaFuncSetAttribute(k_gemm_t,  cudaFuncAttributeMaxDynamicSharedMemorySize, 2 * T_STG);
    cudaFuncSetAttribute(k_gemm_pg, cudaFuncAttributeMaxDynamicSharedMemorySize, 2 * PG_STG);
    cudaFuncSetAttribute(k_yz,      cudaFuncAttributeMaxDynamicSharedMemorySize, 81920);

    k_zero<<<64, 256>>>();
    k_convW<<<dim3(512, 3), 256>>>(Wt, Wp, Wg);
    k_transX<<<dim3(32, 8, 16), 256>>>(x);
    k_wgsum<<<dim3(8, 8), 1024>>>(Wg);
    k_s0<<<128, 256>>>();

    k_gemm_t<<<dim3(8, 4, 16), 256, 2 * T_STG>>>();
    k_gemm_pg<<<dim3(8, 4, 16), 512, 2 * PG_STG>>>();

    dim3 g3(HW_ / 64, G_, B_);
    k_yz<<<g3, 256, 81920>>>(Wz);

    int nblk5 = (B_ * C_ * HW_ / 4 + 255) / 256;
    k_finish<<<nblk5, 256>>>(x, gnw, gnb, out);
}

// round 7
// speedup vs baseline: 4.7135x; 1.0497x over previous
#include <cuda_runtime.h>
#include <cuda_bf16.h>
#include <cuda_fp8.h>
#include <cstdint>
#include <math.h>

typedef unsigned long long ull;

#define B_  16
#define C_  1024
#define P_  512
#define HW_ 1024
#define G_  8

#define WSCALE     64.0f
#define INV_WSCALE 0.015625f

// ---------------- scratch (static device globals; no allocation) ----------------
__device__ __nv_bfloat16 d_t[(size_t)B_ * P_ * HW_];   // 16 MB
__device__ float d_z[(size_t)B_ * C_ * HW_];           // 64 MB
__device__ float d_S[B_ * G_ * 4];                     // moment sums; S0 exact
__device__ float d_gn[B_ * G_ * 2];                    // GN sum / sumsq
__device__ float d_xsum[B_ * C_];                      // per (b,c) spatial sums
__device__ float d_wgsum[G_ * C_];                     // per (g,c) Wg row sums

// fp8 e4m3 operands (W pre-scaled by 64)
__device__ uint8_t d_W8[3u * 512u * 1024u];
__device__ uint8_t d_XT8[(size_t)B_ * 1024u * 1024u];  // [b][n][k]

// ---------------- PTX helpers ----------------
__device__ __forceinline__ uint32_t smem_u32(const void* p) {
    uint32_t a;
    asm("{ .reg .u64 t; cvta.to.shared.u64 t, %1; cvt.u32.u64 %0, t; }" : "=r"(a) : "l"(p));
    return a;
}
#define CP_ASYNC16(sa, ga) \
    asm volatile("cp.async.cg.shared.global [%0], [%1], 16;" :: "r"(sa), "l"(ga))
#define CP_COMMIT()   asm volatile("cp.async.commit_group;" ::: "memory")
#define CP_WAIT(n)    asm volatile("cp.async.wait_group %0;" :: "n"(n) : "memory")

__device__ __forceinline__ void ldsm_x4(uint32_t& r0, uint32_t& r1, uint32_t& r2, uint32_t& r3,
                                        uint32_t addr) {
    asm volatile("ldmatrix.sync.aligned.m8n8.x4.shared.b16 {%0,%1,%2,%3}, [%4];"
                 : "=r"(r0), "=r"(r1), "=r"(r2), "=r"(r3) : "r"(addr));
}
// fp8 e4m3 MMA, k=32
__device__ __forceinline__ void mma16832(float* c, const uint32_t* a, uint32_t b0, uint32_t b1) {
    asm volatile("mma.sync.aligned.m16n8k32.row.col.f32.e4m3.e4m3.f32 "
                 "{%0,%1,%2,%3}, {%4,%5,%6,%7}, {%8,%9}, {%0,%1,%2,%3};"
                 : "+f"(c[0]), "+f"(c[1]), "+f"(c[2]), "+f"(c[3])
                 : "r"(a[0]), "r"(a[1]), "r"(a[2]), "r"(a[3]), "r"(b0), "r"(b1));
}

// packed f32x2 (for k_yz)
__device__ __forceinline__ ull f2fma(ull a, ull b, ull c) {
    ull d; asm("fma.rn.f32x2 %0, %1, %2, %3;" : "=l"(d) : "l"(a), "l"(b), "l"(c)); return d;
}
__device__ __forceinline__ void f2unpack(ull v, float& lo, float& hi) {
    asm("mov.b64 {%0, %1}, %2;" : "=f"(lo), "=f"(hi) : "l"(v));
}

__device__ __forceinline__ uint8_t to_e4m3(float v) {
    return (uint8_t)__nv_cvt_float_to_fp8(v, __NV_SATFINITE, __NV_E4M3);
}

// =====================================================================
// zero accumulators (every launch: graph-replay determinism)
// =====================================================================
__global__ void __launch_bounds__(256) k_zero()
{
    int i = blockIdx.x * 256 + threadIdx.x;
    if (i < B_ * C_)  d_xsum[i]  = 0.f;
    if (i < G_ * C_)  d_wgsum[i] = 0.f;
    if (i < 512)      d_S[i]     = 0.f;
    if (i < 256)      d_gn[i]    = 0.f;
}

// =====================================================================
// W -> fp8 e4m3 (scaled by 64)
// =====================================================================
__global__ void __launch_bounds__(256) k_convW(
    const float* __restrict__ Wt, const float* __restrict__ Wp, const float* __restrict__ Wg)
{
    int w = blockIdx.y;
    const float* W = (w == 0) ? Wt : (w == 1) ? Wp : Wg;
    size_t idx = ((size_t)blockIdx.x * 256 + threadIdx.x) * 4;
    float4 v = *(const float4*)&W[idx];
    uint32_t pk = (uint32_t)to_e4m3(v.x * WSCALE)
                | ((uint32_t)to_e4m3(v.y * WSCALE) << 8)
                | ((uint32_t)to_e4m3(v.z * WSCALE) << 16)
                | ((uint32_t)to_e4m3(v.w * WSCALE) << 24);
    *(uint32_t*)(d_W8 + (size_t)w * 524288u + idx) = pk;
}

// =====================================================================
// X transpose -> fp8 [b][n][k], + exact fp32 channel sums
// =====================================================================
__global__ void __launch_bounds__(256) k_transX(const float* __restrict__ x)
{
    __shared__ float Xs[32][132];
    int k0 = blockIdx.x * 32;
    int n0 = blockIdx.y * 128;
    int b  = blockIdx.z;
    int tid = threadIdx.x;
    const float* xb = x + ((size_t)b * 1024 + k0) * 1024 + n0;
#pragma unroll
    for (int i = 0; i < 4; i++) {
        int slot = tid + i * 256;
        int r  = slot >> 5;
        int c4 = (slot & 31) * 4;
        *(float4*)&Xs[r][c4] = *(const float4*)&xb[(size_t)r * 1024 + c4];
    }
    __syncthreads();

    {
        int r = tid >> 3, q = tid & 7;
        float s = 0.f;
#pragma unroll
        for (int c = 0; c < 16; c++) s += Xs[r][q * 16 + c];
        s += __shfl_down_sync(0xffffffffu, s, 4);
        s += __shfl_down_sync(0xffffffffu, s, 2);
        s += __shfl_down_sync(0xffffffffu, s, 1);
        if (q == 0) atomicAdd(&d_xsum[b * 1024 + k0 + r], s);
    }

    int n  = tid >> 1;
    int kh = (tid & 1) * 16;
    uint32_t pk[4];
#pragma unroll
    for (int j = 0; j < 4; j++) {
        pk[j] = (uint32_t)to_e4m3(Xs[kh + 4 * j + 0][n])
              | ((uint32_t)to_e4m3(Xs[kh + 4 * j + 1][n]) << 8)
              | ((uint32_t)to_e4m3(Xs[kh + 4 * j + 2][n]) << 16)
              | ((uint32_t)to_e4m3(Xs[kh + 4 * j + 3][n]) << 24);
    }
    size_t off = ((size_t)b * 1024 + n0 + n) * 1024 + k0 + kh;
    *(uint4*)(d_XT8 + off) = make_uint4(pk[0], pk[1], pk[2], pk[3]);
}

// =====================================================================
// Wg group-row sums (fp32 exact, 64 blocks)
// =====================================================================
__global__ void __launch_bounds__(1024) k_wgsum(const float* __restrict__ Wg)
{
    int g  = blockIdx.x;
    int rc = blockIdx.y;
    int c  = threadIdx.x;
    const float* base = Wg + ((size_t)g * 64 + rc * 8) * 1024 + c;
    float s = 0.f;
#pragma unroll
    for (int r = 0; r < 8; r++) s += base[(size_t)r * 1024];
    atomicAdd(&d_wgsum[g * 1024 + c], s);
}

// =====================================================================
// Exact S0[b][g] = sum_c wgsum[g][c] * xsum[b][c]
// =====================================================================
__global__ void __launch_bounds__(256) k_s0()
{
    int bg = blockIdx.x;
    int b = bg >> 3, g = bg & 7;
    int tid = threadIdx.x;
    float s = 0.f;
    for (int c = tid; c < 1024; c += 256)
        s += d_wgsum[g * 1024 + c] * d_xsum[b * 1024 + c];
#pragma unroll
    for (int off = 16; off > 0; off >>= 1)
        s += __shfl_down_sync(0xffffffffu, s, off);
    __shared__ float red[8];
    if ((tid & 31) == 0) red[tid >> 5] = s;
    __syncthreads();
    if (tid == 0) {
        float S = 0.f;
#pragma unroll
        for (int i = 0; i < 8; i++) S += red[i];
        d_S[bg * 4 + 0] = S;
    }
}

// =====================================================================
// GEMM-T (fp8): t = Wt @ X.  CTA 128x128, 8 warps (64x32), bf16 out.
// Chunk = 64 k-elements (64 B/row + 16 pad), identical byte layout to
// the old 32-elem bf16 chunk -> same loaders / ldmatrix addressing.
// =====================================================================
#define NCH      16
#define ROWB     80
#define T_TILE_B 10240
#define T_STG    20480
#define T_OFF_A  0
#define T_OFF_B  10240

__device__ __forceinline__ void t_load_chunk(
    uint32_t sb, const uint8_t* gA, const uint8_t* gB, int k0, int tid)
{
#pragma unroll
    for (int i = 0; i < 4; i++) {
        int unit = tid + i * 256;
        int tile = unit >> 9;
        int rem  = unit & 511;
        int r = rem >> 2, u = rem & 3;
        uint32_t dst = sb + (uint32_t)tile * T_TILE_B + (uint32_t)r * ROWB + (uint32_t)u * 16;
        const uint8_t* src = (tile == 0 ? gA : gB) + (size_t)r * 1024 + k0 + u * 16;
        CP_ASYNC16(dst, (const void*)src);
    }
}

__global__ void __launch_bounds__(256, 2) k_gemm_t()
{
    extern __shared__ char smraw[];
    uint32_t sbase = smem_u32(smraw);

    const int tid  = threadIdx.x;
    const int wid  = tid >> 5;
    const int lane = tid & 31;
    const int wm   = wid & 1;
    const int wn   = wid >> 1;

    const int n0 = blockIdx.x * 128;
    const int m0 = blockIdx.y * 128;
    const int b  = blockIdx.z;

    const uint8_t* gA = d_W8 + (size_t)m0 * 1024;
    const uint8_t* gB = d_XT8 + ((size_t)b * 1024 + n0) * 1024;

    float acc[4][4][4];
#pragma unroll
    for (int i = 0; i < 4; i++)
#pragma unroll
        for (int j = 0; j < 4; j++)
#pragma unroll
            for (int q = 0; q < 4; q++) acc[i][j][q] = 0.f;

    const uint32_t aLane = (uint32_t)((wm * 64 + (lane & 15)) * ROWB + (lane >> 4) * 16);
    const int bg = lane >> 3;
    const uint32_t bLane = (uint32_t)((wn * 32 + (bg >> 1) * 8 + (lane & 7)) * ROWB + (bg & 1) * 16);

    t_load_chunk(sbase, gA, gB, 0, tid);
    CP_COMMIT();

    for (int j = 0; j < NCH; j++) {
        const uint32_t sb = sbase + (uint32_t)(j & 1) * T_STG;
        if (j + 1 < NCH) {
            t_load_chunk(sbase + (uint32_t)((j + 1) & 1) * T_STG, gA, gB, (j + 1) * 64, tid);
            CP_COMMIT();
            CP_WAIT(1);
        } else {
            CP_WAIT(0);
        }
        __syncthreads();

#pragma unroll
        for (int s = 0; s < 2; s++) {
            const uint32_t kb = (uint32_t)s * 32;
            uint32_t A[4][4], Bv[4][2];
#pragma unroll
            for (int i = 0; i < 4; i++)
                ldsm_x4(A[i][0], A[i][1], A[i][2], A[i][3],
                        sb + T_OFF_A + aLane + (uint32_t)i * (16 * ROWB) + kb);
#pragma unroll
            for (int jp = 0; jp < 2; jp++)
                ldsm_x4(Bv[jp * 2][0], Bv[jp * 2][1], Bv[jp * 2 + 1][0], Bv[jp * 2 + 1][1],
                        sb + T_OFF_B + bLane + (uint32_t)jp * (16 * ROWB) + kb);
#pragma unroll
            for (int i = 0; i < 4; i++)
#pragma unroll
                for (int jj = 0; jj < 4; jj++)
                    mma16832(acc[i][jj], A[i], Bv[jj][0], Bv[jj][1]);
        }
        __syncthreads();
    }

    // epilogue -> bf16 (unscale W factor)
    {
        const int rbase = m0 + wm * 64 + (lane >> 2);
        const int cbase = n0 + wn * 32 + (lane & 3) * 2;
        __nv_bfloat16* ob = d_t + (size_t)b * 512 * 1024;
#pragma unroll
        for (int i = 0; i < 4; i++) {
#pragma unroll
            for (int jj = 0; jj < 4; jj++) {
                size_t r0 = (size_t)(rbase + i * 16) * 1024 + cbase + jj * 8;
                __nv_bfloat162 v0 = __floats2bfloat162_rn(acc[i][jj][0] * INV_WSCALE,
                                                          acc[i][jj][1] * INV_WSCALE);
                __nv_bfloat162 v1 = __floats2bfloat162_rn(acc[i][jj][2] * INV_WSCALE,
                                                          acc[i][jj][3] * INV_WSCALE);
                *(uint32_t*)(ob + r0)            = *(uint32_t*)&v0;
                *(uint32_t*)(ob + r0 + 8 * 1024) = *(uint32_t*)&v1;
            }
        }
    }
}

// =====================================================================
// GEMM-PG (fp8): CTA 128m x 128n, 512 thr / 16 warps (warp 32x32), dual
// p/g accumulators; epilogue reduces S1..S3 via atomicAdd.
// =====================================================================
#define PG_OFF_AP  0
#define PG_OFF_AG  10240
#define PG_OFF_B   20480
#define PG_STG     30720

__device__ __forceinline__ void pg_load_chunk(
    uint32_t sb, const uint8_t* gAp, const uint8_t* gAg,
    const uint8_t* gB, int k0, int tid)
{
    const uint8_t* srcs[3] = {gAp, gAg, gB};
#pragma unroll
    for (int i = 0; i < 3; i++) {
        int r = tid >> 2, u = tid & 3;
        uint32_t dst = sb + (uint32_t)i * T_TILE_B + (uint32_t)r * ROWB + (uint32_t)u * 16;
        CP_ASYNC16(dst, (const void*)(srcs[i] + (size_t)r * 1024 + k0 + u * 16));
    }
}

__global__ void __launch_bounds__(512, 1) k_gemm_pg()
{
    extern __shared__ char smraw[];
    uint32_t sbase = smem_u32(smraw);

    const int tid  = threadIdx.x;
    const int wid  = tid >> 5;
    const int lane = tid & 31;
    const int wm   = wid & 3;
    const int wn   = wid >> 2;

    const int n0 = blockIdx.x * 128;
    const int m0 = blockIdx.y * 128;
    const int b  = blockIdx.z;

    const uint8_t* gAp = d_W8 + 1u * 524288u + (size_t)m0 * 1024;
    const uint8_t* gAg = d_W8 + 2u * 524288u + (size_t)m0 * 1024;
    const uint8_t* gB  = d_XT8 + ((size_t)b * 1024 + n0) * 1024;

    float accp[2][4][4], accg[2][4][4];
#pragma unroll
    for (int i = 0; i < 2; i++)
#pragma unroll
        for (int j = 0; j < 4; j++)
#pragma unroll
            for (int q = 0; q < 4; q++) { accp[i][j][q] = 0.f; accg[i][j][q] = 0.f; }

    const uint32_t aLane = (uint32_t)((wm * 32 + (lane & 15)) * ROWB + (lane >> 4) * 16);
    const int bgrp = lane >> 3;
    const uint32_t bLane = (uint32_t)((wn * 32 + (bgrp >> 1) * 8 + (lane & 7)) * ROWB + (bgrp & 1) * 16);

    pg_load_chunk(sbase, gAp, gAg, gB, 0, tid);
    CP_COMMIT();

    for (int j = 0; j < NCH; j++) {
        const uint32_t sb = sbase + (uint32_t)(j & 1) * PG_STG;
        if (j + 1 < NCH) {
            pg_load_chunk(sbase + (uint32_t)((j + 1) & 1) * PG_STG, gAp, gAg, gB, (j + 1) * 64, tid);
            CP_COMMIT();
            CP_WAIT(1);
        } else {
            CP_WAIT(0);
        }
        __syncthreads();

#pragma unroll
        for (int s = 0; s < 2; s++) {
            const uint32_t kb = (uint32_t)s * 32;
            uint32_t Ap[2][4], Ag[2][4], Bv[4][2];
#pragma unroll
            for (int i = 0; i < 2; i++) {
                ldsm_x4(Ap[i][0], Ap[i][1], Ap[i][2], Ap[i][3],
                        sb + PG_OFF_AP + aLane + (uint32_t)i * (16 * ROWB) + kb);
                ldsm_x4(Ag[i][0], Ag[i][1], Ag[i][2], Ag[i][3],
                        sb + PG_OFF_AG + aLane + (uint32_t)i * (16 * ROWB) + kb);
            }
#pragma unroll
            for (int jp = 0; jp < 2; jp++)
                ldsm_x4(Bv[jp * 2][0], Bv[jp * 2][1], Bv[jp * 2 + 1][0], Bv[jp * 2 + 1][1],
                        sb + PG_OFF_B + bLane + (uint32_t)jp * (16 * ROWB) + kb);
#pragma unroll
            for (int i = 0; i < 2; i++)
#pragma unroll
                for (int jj = 0; jj < 4; jj++) {
                    mma16832(accp[i][jj], Ap[i], Bv[jj][0], Bv[jj][1]);
                    mma16832(accg[i][jj], Ag[i], Bv[jj][0], Bv[jj][1]);
                }
        }
        __syncthreads();
    }

    // moment epilogue (S1..S3; unscale W factor on p and g)
    {
        float s1 = 0.f, s2 = 0.f, s3 = 0.f;
#pragma unroll
        for (int i = 0; i < 2; i++)
#pragma unroll
            for (int jj = 0; jj < 4; jj++)
#pragma unroll
                for (int q = 0; q < 4; q++) {
                    float pv = accp[i][jj][q] * INV_WSCALE;
                    float gv = accg[i][jj][q] * INV_WSCALE;
                    float t1 = pv * gv; s1 += t1;
                    t1 *= pv; s2 += t1;
                    t1 *= pv; s3 += t1;
                }
#pragma unroll
        for (int off = 16; off > 0; off >>= 1) {
            s1 += __shfl_down_sync(0xffffffffu, s1, off);
            s2 += __shfl_down_sync(0xffffffffu, s2, off);
            s3 += __shfl_down_sync(0xffffffffu, s3, off);
        }
        if (lane == 0) {
            int g = (m0 >> 6) + (wm >> 1);
            float* Sp = d_S + (b * 8 + g) * 4;
            atomicAdd(Sp + 1, s1);
            atomicAdd(Sp + 2, s2);
            atomicAdd(Sp + 3, s3);
        }
    }
}

// =====================================================================
// y = poly(t), z = Wz @ y (K=64), + inline GroupNorm partial sums.
// =====================================================================
__global__ void __launch_bounds__(256) k_yz(const float* __restrict__ Wz)
{
    extern __shared__ char sm3[];
    float*  Ys  = (float*)sm3;
    float2* Wzd = (float2*)(sm3 + 64 * 64 * 4);

    const int n0 = blockIdx.x * 64;
    const int g  = blockIdx.y;
    const int b  = blockIdx.z;
    const int tid = threadIdx.x;
    const int tx = tid & 15;
    const int ty = tid >> 4;
    const int bgidx = b * 8 + g;

    const float tg   = 2.0f * 1e-4f;
    const float beta = expf(-tg);
    const float c0 = beta * d_S[bgidx * 4 + 0];
    const float c1 = beta * tg * d_S[bgidx * 4 + 1];
    const float c2 = beta * (tg * tg * 0.5f) * d_S[bgidx * 4 + 2];
    const float c3 = beta * (tg * tg * tg * (1.f / 6.f)) * d_S[bgidx * 4 + 3];

    const float* Wzg = Wz + g * (128 * 64);
    for (int s = tid; s < 8192; s += 256) {
        float w = Wzg[s];
        Wzd[s] = make_float2(w, w);
    }
    const __nv_bfloat16* tb = d_t + ((size_t)b * P_ + g * 64) * HW_ + n0;
    for (int s = tid; s < 1024; s += 256) {
        int i  = s >> 4;
        int c4 = (s & 15) << 2;
        uint2 raw = *(const uint2*)&tb[(size_t)i * HW_ + c4];
        __nv_bfloat162 t01 = *(__nv_bfloat162*)&raw.x;
        __nv_bfloat162 t23 = *(__nv_bfloat162*)&raw.y;
        float4 tv;
        tv.x = __low2float(t01); tv.y = __high2float(t01);
        tv.z = __low2float(t23); tv.w = __high2float(t23);
        float4 yv;
        yv.x = ((c3 * tv.x + c2) * tv.x + c1) * tv.x + c0;
        yv.y = ((c3 * tv.y + c2) * tv.y + c1) * tv.y + c0;
        yv.z = ((c3 * tv.z + c2) * tv.z + c1) * tv.z + c0;
        yv.w = ((c3 * tv.w + c2) * tv.w + c1) * tv.w + c0;
        *(float4*)&Ys[i * 64 + c4] = yv;
    }
    __syncthreads();

    ull acc[8][2];
#pragma unroll
    for (int j = 0; j < 8; j++) { acc[j][0] = 0ULL; acc[j][1] = 0ULL; }

#pragma unroll 8
    for (int kk = 0; kk < 64; kk++) {
        ull xp0 = *(const ull*)&Ys[kk * 64 + tx * 4];
        ull xp1 = *(const ull*)&Ys[kk * 64 + tx * 4 + 2];
#pragma unroll
        for (int j = 0; j < 8; j++) {
            ull wd = *(const ull*)&Wzd[(ty * 8 + j) * 64 + kk];
            acc[j][0] = f2fma(wd, xp0, acc[j][0]);
            acc[j][1] = f2fma(wd, xp1, acc[j][1]);
        }
    }

    float* zb = d_z + ((size_t)b * C_ + g * 128) * HW_ + n0;
    float ls = 0.f, lss = 0.f;
#pragma unroll
    for (int j = 0; j < 8; j++) {
        float4 v;
        f2unpack(acc[j][0], v.x, v.y);
        f2unpack(acc[j][1], v.z, v.w);
        *(float4*)&zb[(size_t)(ty * 8 + j) * HW_ + tx * 4] = v;
        ls  += (v.x + v.y) + (v.z + v.w);
        lss += v.x * v.x + v.y * v.y + v.z * v.z + v.w * v.w;
    }
#pragma unroll
    for (int off = 16; off > 0; off >>= 1) {
        ls  += __shfl_down_sync(0xffffffffu, ls, off);
        lss += __shfl_down_sync(0xffffffffu, lss, off);
    }
    __shared__ float red[2][8];
    int lane = tid & 31, wrp = tid >> 5;
    if (lane == 0) { red[0][wrp] = ls; red[1][wrp] = lss; }
    __syncthreads();
    if (tid == 0) {
        float S = 0.f, SS = 0.f;
#pragma unroll
        for (int i = 0; i < 8; i++) { S += red[0][i]; SS += red[1][i]; }
        atomicAdd(&d_gn[bgidx * 2 + 0], S);
        atomicAdd(&d_gn[bgidx * 2 + 1], SS);
    }
}

// =====================================================================
// finish: out = (z - mean)*rstd*gn_w + gn_b + x
// =====================================================================
__global__ void __launch_bounds__(256) k_finish(
    const float* __restrict__ x, const float* __restrict__ gn_w,
    const float* __restrict__ gn_b, float* __restrict__ out)
{
    int i4 = blockIdx.x * 256 + threadIdx.x;
    if (i4 >= (B_ * C_ * HW_) / 4) return;
    size_t idx = (size_t)i4 * 4;
    int ch = (int)((idx >> 10) & 1023);
    int b  = (int)(idx >> 20);
    int bg = b * 8 + (ch >> 7);
    const float invN = 1.0f / 131072.0f;
    float s  = d_gn[bg * 2 + 0];
    float ss = d_gn[bg * 2 + 1];
    float mean = s * invN;
    float var  = ss * invN - mean * mean;
    float rstd = rsqrtf(var + 1e-5f);
    float a = gn_w[ch] * rstd;
    float c = gn_b[ch] - mean * a;
    float4 zv = *(const float4*)&d_z[idx];
    float4 xv = *(const float4*)&x[idx];
    float4 o;
    o.x = zv.x * a + c + xv.x;
    o.y = zv.y * a + c + xv.y;
    o.z = zv.z * a + c + xv.z;
    o.w = zv.w * a + c + xv.w;
    *(float4*)&out[idx] = o;
}

// =====================================================================
extern "C" void kernel_launch(void* const* d_in, const int* in_sizes, int n_in,
                              void* d_out, int out_size)
{
    const float* x   = (const float*)d_in[0];
    const float* Wt  = (const float*)d_in[1];
    const float* Wp  = (const float*)d_in[2];
    const float* Wg  = (const float*)d_in[3];
    const float* Wz  = (const float*)d_in[4];
    const float* gnw = (const float*)d_in[5];
    const float* gnb = (const float*)d_in[6];
    float* out = (float*)d_out;

    cudaFuncSetAttribute(k_gemm_t,  cudaFuncAttributeMaxDynamicSharedMemorySize, 2 * T_STG);
    cudaFuncSetAttribute(k_gemm_pg, cudaFuncAttributeMaxDynamicSharedMemorySize, 2 * PG_STG);
    cudaFuncSetAttribute(k_yz,      cudaFuncAttributeMaxDynamicSharedMemorySize, 81920);

    k_zero<<<64, 256>>>();
    k_convW<<<dim3(512, 3), 256>>>(Wt, Wp, Wg);
    k_transX<<<dim3(32, 8, 16), 256>>>(x);
    k_wgsum<<<dim3(8, 8), 1024>>>(Wg);
    k_s0<<<128, 256>>>();

    k_gemm_t<<<dim3(8, 4, 16), 256, 2 * T_STG>>>();
    k_gemm_pg<<<dim3(8, 4, 16), 512, 2 * PG_STG>>>();

    dim3 g3(HW_ / 64, G_, B_);
    k_yz<<<g3, 256, 81920>>>(Wz);

    int nblk5 = (B_ * C_ * HW_ / 4 + 255) / 256;
    k_finish<<<nblk5, 256>>>(x, gnw, gnb, out);
}

// round 8
// speedup vs baseline: 5.1030x; 1.0826x over previous
#include <cuda_runtime.h>
#include <cuda_bf16.h>
#include <cuda_fp16.h>
#include <cuda_fp8.h>
#include <cstdint>
#include <math.h>

typedef unsigned long long ull;

#define B_  16
#define C_  1024
#define P_  512
#define HW_ 1024
#define G_  8

#define WSCALE     64.0f
#define INV_WSCALE 0.015625f

// ---------------- scratch (static device globals; no allocation) ----------------
__device__ __nv_bfloat16 d_tT[(size_t)B_ * HW_ * P_];  // 16 MB, [b][n][ch] transposed
__device__ __half d_z16[(size_t)B_ * C_ * HW_];        // 32 MB fp16
__device__ float d_S[B_ * G_ * 4];                     // moment sums; S0 exact
__device__ float d_gn[B_ * G_ * 2];                    // GN sum / sumsq
__device__ float d_xsum[B_ * C_];                      // per (b,c) spatial sums
__device__ float d_wgsum[G_ * C_];                     // per (g,c) Wg row sums
__device__ float d_wzrs[G_ * 128];                     // rowsum of Wz per (g,oc)

// quantized operands
__device__ uint8_t d_W8[3u * 512u * 1024u];            // fp8 W (x64)
__device__ uint8_t d_XT8[(size_t)B_ * 1024u * 1024u];  // fp8 X^T [b][n][k]
__device__ __nv_bfloat16 d_Wz16[G_ * 128 * 64];        // bf16 Wz

// ---------------- PTX helpers ----------------
__device__ __forceinline__ uint32_t smem_u32(const void* p) {
    uint32_t a;
    asm("{ .reg .u64 t; cvta.to.shared.u64 t, %1; cvt.u32.u64 %0, t; }" : "=r"(a) : "l"(p));
    return a;
}
#define CP_ASYNC16(sa, ga) \
    asm volatile("cp.async.cg.shared.global [%0], [%1], 16;" :: "r"(sa), "l"(ga))
#define CP_COMMIT()   asm volatile("cp.async.commit_group;" ::: "memory")
#define CP_WAIT(n)    asm volatile("cp.async.wait_group %0;" :: "n"(n) : "memory")

__device__ __forceinline__ void ldsm_x4(uint32_t& r0, uint32_t& r1, uint32_t& r2, uint32_t& r3,
                                        uint32_t addr) {
    asm volatile("ldmatrix.sync.aligned.m8n8.x4.shared.b16 {%0,%1,%2,%3}, [%4];"
                 : "=r"(r0), "=r"(r1), "=r"(r2), "=r"(r3) : "r"(addr));
}
__device__ __forceinline__ void mma16832(float* c, const uint32_t* a, uint32_t b0, uint32_t b1) {
    asm volatile("mma.sync.aligned.m16n8k32.row.col.f32.e4m3.e4m3.f32 "
                 "{%0,%1,%2,%3}, {%4,%5,%6,%7}, {%8,%9}, {%0,%1,%2,%3};"
                 : "+f"(c[0]), "+f"(c[1]), "+f"(c[2]), "+f"(c[3])
                 : "r"(a[0]), "r"(a[1]), "r"(a[2]), "r"(a[3]), "r"(b0), "r"(b1));
}
__device__ __forceinline__ void mma16816(float* c, const uint32_t* a, uint32_t b0, uint32_t b1) {
    asm volatile("mma.sync.aligned.m16n8k16.row.col.f32.bf16.bf16.f32 "
                 "{%0,%1,%2,%3}, {%4,%5,%6,%7}, {%8,%9}, {%0,%1,%2,%3};"
                 : "+f"(c[0]), "+f"(c[1]), "+f"(c[2]), "+f"(c[3])
                 : "r"(a[0]), "r"(a[1]), "r"(a[2]), "r"(a[3]), "r"(b0), "r"(b1));
}
__device__ __forceinline__ uint8_t to_e4m3(float v) {
    return (uint8_t)__nv_cvt_float_to_fp8(v, __NV_SATFINITE, __NV_E4M3);
}

// =====================================================================
// k_prep: fused prepass — roles by blockIdx.x
//   [0,1536): W -> fp8      [1536]: zero accums
//   [1537,1569): Wg group-row sums   [1569,1601): Wz -> bf16   [1601]: Wz rowsums
// =====================================================================
__global__ void __launch_bounds__(256) k_prep(
    const float* __restrict__ Wt, const float* __restrict__ Wp,
    const float* __restrict__ Wg, const float* __restrict__ Wz)
{
    int bx = blockIdx.x, tid = threadIdx.x;
    if (bx < 1536) {
        int w = bx >> 9, inner = bx & 511;
        const float* W = (w == 0) ? Wt : (w == 1) ? Wp : Wg;
        size_t idx = ((size_t)inner * 256 + tid) * 4;
        float4 v = *(const float4*)&W[idx];
        uint32_t pk = (uint32_t)to_e4m3(v.x * WSCALE)
                    | ((uint32_t)to_e4m3(v.y * WSCALE) << 8)
                    | ((uint32_t)to_e4m3(v.z * WSCALE) << 16)
                    | ((uint32_t)to_e4m3(v.w * WSCALE) << 24);
        *(uint32_t*)(d_W8 + (size_t)w * 524288u + idx) = pk;
    } else if (bx == 1536) {
        for (int i = tid; i < B_ * C_; i += 256) d_xsum[i] = 0.f;
        for (int i = tid; i < 512; i += 256)     d_S[i]    = 0.f;
        if (tid < 256)                            d_gn[tid] = 0.f;
    } else if (bx < 1569) {
        int idx = bx - 1537;
        int g = idx >> 2, c = (idx & 3) * 256 + tid;
        const float* base = Wg + (size_t)g * 64 * 1024 + c;
        float s = 0.f;
#pragma unroll 8
        for (int r = 0; r < 64; r++) s += base[(size_t)r * 1024];
        d_wgsum[g * 1024 + c] = s;
    } else if (bx < 1601) {
        int idx = bx - 1569;                 // 0..31, 2048 floats each
        int base = idx * 2048 + tid * 8;
        float4 v0 = *(const float4*)&Wz[base];
        float4 v1 = *(const float4*)&Wz[base + 4];
        __nv_bfloat162 h0 = __floats2bfloat162_rn(v0.x, v0.y);
        __nv_bfloat162 h1 = __floats2bfloat162_rn(v0.z, v0.w);
        __nv_bfloat162 h2 = __floats2bfloat162_rn(v1.x, v1.y);
        __nv_bfloat162 h3 = __floats2bfloat162_rn(v1.z, v1.w);
        uint4 pk = make_uint4(*(uint32_t*)&h0, *(uint32_t*)&h1,
                              *(uint32_t*)&h2, *(uint32_t*)&h3);
        *(uint4*)(d_Wz16 + base) = pk;
    } else {
        for (int oc = tid; oc < 1024; oc += 256) {
            const float* p = Wz + (size_t)oc * 64;
            float s = 0.f;
#pragma unroll
            for (int k = 0; k < 64; k++) s += p[k];
            d_wzrs[oc] = s;
        }
    }
}

// =====================================================================
// X transpose -> fp8 [b][n][k], + exact fp32 channel sums
// =====================================================================
__global__ void __launch_bounds__(256) k_transX(const float* __restrict__ x)
{
    __shared__ float Xs[32][132];
    int k0 = blockIdx.x * 32;
    int n0 = blockIdx.y * 128;
    int b  = blockIdx.z;
    int tid = threadIdx.x;
    const float* xb = x + ((size_t)b * 1024 + k0) * 1024 + n0;
#pragma unroll
    for (int i = 0; i < 4; i++) {
        int slot = tid + i * 256;
        int r  = slot >> 5;
        int c4 = (slot & 31) * 4;
        *(float4*)&Xs[r][c4] = *(const float4*)&xb[(size_t)r * 1024 + c4];
    }
    __syncthreads();

    {
        int r = tid >> 3, q = tid & 7;
        float s = 0.f;
#pragma unroll
        for (int c = 0; c < 16; c++) s += Xs[r][q * 16 + c];
        s += __shfl_down_sync(0xffffffffu, s, 4);
        s += __shfl_down_sync(0xffffffffu, s, 2);
        s += __shfl_down_sync(0xffffffffu, s, 1);
        if (q == 0) atomicAdd(&d_xsum[b * 1024 + k0 + r], s);
    }

    int n  = tid >> 1;
    int kh = (tid & 1) * 16;
    uint32_t pk[4];
#pragma unroll
    for (int j = 0; j < 4; j++) {
        pk[j] = (uint32_t)to_e4m3(Xs[kh + 4 * j + 0][n])
              | ((uint32_t)to_e4m3(Xs[kh + 4 * j + 1][n]) << 8)
              | ((uint32_t)to_e4m3(Xs[kh + 4 * j + 2][n]) << 16)
              | ((uint32_t)to_e4m3(Xs[kh + 4 * j + 3][n]) << 24);
    }
    size_t off = ((size_t)b * 1024 + n0 + n) * 1024 + k0 + kh;
    *(uint4*)(d_XT8 + off) = make_uint4(pk[0], pk[1], pk[2], pk[3]);
}

// =====================================================================
// Exact S0[b][g] = sum_c wgsum[g][c] * xsum[b][c]
// =====================================================================
__global__ void __launch_bounds__(256) k_s0()
{
    int bg = blockIdx.x;
    int b = bg >> 3, g = bg & 7;
    int tid = threadIdx.x;
    float s = 0.f;
    for (int c = tid; c < 1024; c += 256)
        s += d_wgsum[g * 1024 + c] * d_xsum[b * 1024 + c];
#pragma unroll
    for (int off = 16; off > 0; off >>= 1)
        s += __shfl_down_sync(0xffffffffu, s, off);
    __shared__ float red[8];
    if ((tid & 31) == 0) red[tid >> 5] = s;
    __syncthreads();
    if (tid == 0) {
        float S = 0.f;
#pragma unroll
        for (int i = 0; i < 8; i++) S += red[i];
        d_S[bg * 4 + 0] = S;
    }
}

// =====================================================================
// GEMM-T (fp8): t = Wt @ X.  CTA 128x128, 8 warps (64x32).
// Epilogue: smem-staged TRANSPOSE -> d_tT[b][n][ch] in bf16.
// =====================================================================
#define NCH      16
#define ROWB     80
#define T_TILE_B 10240
#define T_STG    20480
#define T_OFF_A  0
#define T_OFF_B  10240
#define TSROW    136            // bf16 elements per transpose-stage row

__device__ __forceinline__ void t_load_chunk(
    uint32_t sb, const uint8_t* gA, const uint8_t* gB, int k0, int tid)
{
#pragma unroll
    for (int i = 0; i < 4; i++) {
        int unit = tid + i * 256;
        int tile = unit >> 9;
        int rem  = unit & 511;
        int r = rem >> 2, u = rem & 3;
        uint32_t dst = sb + (uint32_t)tile * T_TILE_B + (uint32_t)r * ROWB + (uint32_t)u * 16;
        const uint8_t* src = (tile == 0 ? gA : gB) + (size_t)r * 1024 + k0 + u * 16;
        CP_ASYNC16(dst, (const void*)src);
    }
}

__global__ void __launch_bounds__(256, 2) k_gemm_t()
{
    extern __shared__ char smraw[];
    uint32_t sbase = smem_u32(smraw);

    const int tid  = threadIdx.x;
    const int wid  = tid >> 5;
    const int lane = tid & 31;
    const int wm   = wid & 1;
    const int wn   = wid >> 1;

    const int n0 = blockIdx.x * 128;
    const int m0 = blockIdx.y * 128;
    const int b  = blockIdx.z;

    const uint8_t* gA = d_W8 + (size_t)m0 * 1024;
    const uint8_t* gB = d_XT8 + ((size_t)b * 1024 + n0) * 1024;

    float acc[4][4][4];
#pragma unroll
    for (int i = 0; i < 4; i++)
#pragma unroll
        for (int j = 0; j < 4; j++)
#pragma unroll
            for (int q = 0; q < 4; q++) acc[i][j][q] = 0.f;

    const uint32_t aLane = (uint32_t)((wm * 64 + (lane & 15)) * ROWB + (lane >> 4) * 16);
    const int bg = lane >> 3;
    const uint32_t bLane = (uint32_t)((wn * 32 + (bg >> 1) * 8 + (lane & 7)) * ROWB + (bg & 1) * 16);

    t_load_chunk(sbase, gA, gB, 0, tid);
    CP_COMMIT();

    for (int j = 0; j < NCH; j++) {
        const uint32_t sb = sbase + (uint32_t)(j & 1) * T_STG;
        if (j + 1 < NCH) {
            t_load_chunk(sbase + (uint32_t)((j + 1) & 1) * T_STG, gA, gB, (j + 1) * 64, tid);
            CP_COMMIT();
            CP_WAIT(1);
        } else {
            CP_WAIT(0);
        }
        __syncthreads();

#pragma unroll
        for (int s = 0; s < 2; s++) {
            const uint32_t kb = (uint32_t)s * 32;
            uint32_t A[4][4], Bv[4][2];
#pragma unroll
            for (int i = 0; i < 4; i++)
                ldsm_x4(A[i][0], A[i][1], A[i][2], A[i][3],
                        sb + T_OFF_A + aLane + (uint32_t)i * (16 * ROWB) + kb);
#pragma unroll
            for (int jp = 0; jp < 2; jp++)
                ldsm_x4(Bv[jp * 2][0], Bv[jp * 2][1], Bv[jp * 2 + 1][0], Bv[jp * 2 + 1][1],
                        sb + T_OFF_B + bLane + (uint32_t)jp * (16 * ROWB) + kb);
#pragma unroll
            for (int i = 0; i < 4; i++)
#pragma unroll
                for (int jj = 0; jj < 4; jj++)
                    mma16832(acc[i][jj], A[i], Bv[jj][0], Bv[jj][1]);
        }
        __syncthreads();
    }

    // ---- transpose epilogue via smem stage (pipeline buffers are free now) ----
    {
        __nv_bfloat16* Ts = (__nv_bfloat16*)smraw;   // 128 x TSROW bf16 = 34816 B
        const int mloc = wm * 64 + (lane >> 2);
        const int nloc = wn * 32 + (lane & 3) * 2;
#pragma unroll
        for (int i = 0; i < 4; i++)
#pragma unroll
            for (int jj = 0; jj < 4; jj++)
#pragma unroll
                for (int q = 0; q < 4; q++) {
                    int m = mloc + i * 16 + ((q >> 1) << 3);
                    int n = nloc + jj * 8 + (q & 1);
                    Ts[n * TSROW + m] = __float2bfloat16(acc[i][jj][q] * INV_WSCALE);
                }
        __syncthreads();
        int n  = tid >> 1;
        int mh = (tid & 1) * 64;
        const uint4* src = (const uint4*)(Ts + n * TSROW + mh);
        __nv_bfloat16* dst = d_tT + ((size_t)(b * 1024 + n0 + n)) * 512 + m0 + mh;
#pragma unroll
        for (int u = 0; u < 8; u++)
            ((uint4*)dst)[u] = src[u];
    }
}

// =====================================================================
// GEMM-PG (fp8): CTA 128m x 128n, 512 thr / 16 warps (warp 32x32), dual
// p/g accumulators; epilogue reduces S1..S3 via atomicAdd.
// =====================================================================
#define PG_OFF_AP  0
#define PG_OFF_AG  10240
#define PG_OFF_B   20480
#define PG_STG     30720

__device__ __forceinline__ void pg_load_chunk(
    uint32_t sb, const uint8_t* gAp, const uint8_t* gAg,
    const uint8_t* gB, int k0, int tid)
{
    const uint8_t* srcs[3] = {gAp, gAg, gB};
#pragma unroll
    for (int i = 0; i < 3; i++) {
        int r = tid >> 2, u = tid & 3;
        uint32_t dst = sb + (uint32_t)i * T_TILE_B + (uint32_t)r * ROWB + (uint32_t)u * 16;
        CP_ASYNC16(dst, (const void*)(srcs[i] + (size_t)r * 1024 + k0 + u * 16));
    }
}

__global__ void __launch_bounds__(512, 1) k_gemm_pg()
{
    extern __shared__ char smraw[];
    uint32_t sbase = smem_u32(smraw);

    const int tid  = threadIdx.x;
    const int wid  = tid >> 5;
    const int lane = tid & 31;
    const int wm   = wid & 3;
    const int wn   = wid >> 2;

    const int n0 = blockIdx.x * 128;
    const int m0 = blockIdx.y * 128;
    const int b  = blockIdx.z;

    const uint8_t* gAp = d_W8 + 1u * 524288u + (size_t)m0 * 1024;
    const uint8_t* gAg = d_W8 + 2u * 524288u + (size_t)m0 * 1024;
    const uint8_t* gB  = d_XT8 + ((size_t)b * 1024 + n0) * 1024;

    float accp[2][4][4], accg[2][4][4];
#pragma unroll
    for (int i = 0; i < 2; i++)
#pragma unroll
        for (int j = 0; j < 4; j++)
#pragma unroll
            for (int q = 0; q < 4; q++) { accp[i][j][q] = 0.f; accg[i][j][q] = 0.f; }

    const uint32_t aLane = (uint32_t)((wm * 32 + (lane & 15)) * ROWB + (lane >> 4) * 16);
    const int bgrp = lane >> 3;
    const uint32_t bLane = (uint32_t)((wn * 32 + (bgrp >> 1) * 8 + (lane & 7)) * ROWB + (bgrp & 1) * 16);

    pg_load_chunk(sbase, gAp, gAg, gB, 0, tid);
    CP_COMMIT();

    for (int j = 0; j < NCH; j++) {
        const uint32_t sb = sbase + (uint32_t)(j & 1) * PG_STG;
        if (j + 1 < NCH) {
            pg_load_chunk(sbase + (uint32_t)((j + 1) & 1) * PG_STG, gAp, gAg, gB, (j + 1) * 64, tid);
            CP_COMMIT();
            CP_WAIT(1);
        } else {
            CP_WAIT(0);
        }
        __syncthreads();

#pragma unroll
        for (int s = 0; s < 2; s++) {
            const uint32_t kb = (uint32_t)s * 32;
            uint32_t Ap[2][4], Ag[2][4], Bv[4][2];
#pragma unroll
            for (int i = 0; i < 2; i++) {
                ldsm_x4(Ap[i][0], Ap[i][1], Ap[i][2], Ap[i][3],
                        sb + PG_OFF_AP + aLane + (uint32_t)i * (16 * ROWB) + kb);
                ldsm_x4(Ag[i][0], Ag[i][1], Ag[i][2], Ag[i][3],
                        sb + PG_OFF_AG + aLane + (uint32_t)i * (16 * ROWB) + kb);
            }
#pragma unroll
            for (int jp = 0; jp < 2; jp++)
                ldsm_x4(Bv[jp * 2][0], Bv[jp * 2][1], Bv[jp * 2 + 1][0], Bv[jp * 2 + 1][1],
                        sb + PG_OFF_B + bLane + (uint32_t)jp * (16 * ROWB) + kb);
#pragma unroll
            for (int i = 0; i < 2; i++)
#pragma unroll
                for (int jj = 0; jj < 4; jj++) {
                    mma16832(accp[i][jj], Ap[i], Bv[jj][0], Bv[jj][1]);
                    mma16832(accg[i][jj], Ag[i], Bv[jj][0], Bv[jj][1]);
                }
        }
        __syncthreads();
    }

    {
        float s1 = 0.f, s2 = 0.f, s3 = 0.f;
#pragma unroll
        for (int i = 0; i < 2; i++)
#pragma unroll
            for (int jj = 0; jj < 4; jj++)
#pragma unroll
                for (int q = 0; q < 4; q++) {
                    float pv = accp[i][jj][q] * INV_WSCALE;
                    float gv = accg[i][jj][q] * INV_WSCALE;
                    float t1 = pv * gv; s1 += t1;
                    t1 *= pv; s2 += t1;
                    t1 *= pv; s3 += t1;
                }
#pragma unroll
        for (int off = 16; off > 0; off >>= 1) {
            s1 += __shfl_down_sync(0xffffffffu, s1, off);
            s2 += __shfl_down_sync(0xffffffffu, s2, off);
            s3 += __shfl_down_sync(0xffffffffu, s3, off);
        }
        if (lane == 0) {
            int g = (m0 >> 6) + (wm >> 1);
            float* Sp = d_S + (b * 8 + g) * 4;
            atomicAdd(Sp + 1, s1);
            atomicAdd(Sp + 2, s2);
            atomicAdd(Sp + 3, s3);
        }
    }
}

// =====================================================================
// k_yz (HMMA): z = c0*rowsum(Wz) + c1*(Wz @ y''), y'' = t + a2 t^2 + a3 t^3.
// One K=64 bf16 MMA tile per (b, g, 128n). 8 warps, warp 64oc x 32n.
// Writes z in fp16 + GN partial sums.
// =====================================================================
#define YZ_ROWB  144
#define YZ_BOFF  (128 * 144)      // 18432; total dyn smem 36864

__global__ void __launch_bounds__(256) k_yz()
{
    extern __shared__ char sm3[];
    uint32_t sA = smem_u32(sm3);
    uint32_t sB = sA + YZ_BOFF;

    const int n0 = blockIdx.x * 128;
    const int g  = blockIdx.y;
    const int b  = blockIdx.z;
    const int tid = threadIdx.x;
    const int wid = tid >> 5, lane = tid & 31;
    const int wm = wid & 1, wn = wid >> 1;
    const int bgidx = b * 8 + g;

    const float tg   = 2.0f * 1e-4f;
    const float beta = expf(-tg);
    const float c0 = beta * d_S[bgidx * 4 + 0];
    const float c1 = beta * tg * d_S[bgidx * 4 + 1];
    const float c2 = beta * (tg * tg * 0.5f) * d_S[bgidx * 4 + 2];
    const float c3 = beta * (tg * tg * tg * (1.f / 6.f)) * d_S[bgidx * 4 + 3];
    const float a2 = c2 / c1, a3 = c3 / c1;

    // async tile loads: A = Wz16[g] (128oc x 64k), B = tT (128n x 64ch)
#pragma unroll
    for (int i = 0; i < 4; i++) {
        int unit = tid + i * 256;           // 0..1023
        int r = unit >> 3, u = unit & 7;
        CP_ASYNC16(sA + r * YZ_ROWB + u * 16,
                   (const void*)(d_Wz16 + g * 8192 + r * 64 + u * 8));
        CP_ASYNC16(sB + r * YZ_ROWB + u * 16,
                   (const void*)(d_tT + ((size_t)(b * 1024 + n0 + r)) * 512 + g * 64 + u * 8));
    }
    CP_COMMIT();
    CP_WAIT(0);
    __syncthreads();

    // transform B in place: y'' = t*(1 + a2*t + a3*t^2)
#pragma unroll
    for (int i = 0; i < 4; i++) {
        int unit = tid + i * 256;
        int r = unit >> 3, u = unit & 7;
        __nv_bfloat16* p = (__nv_bfloat16*)(sm3 + YZ_BOFF + r * YZ_ROWB + u * 16);
        uint4 raw = *(uint4*)p;
        uint32_t w[4] = {raw.x, raw.y, raw.z, raw.w};
#pragma unroll
        for (int q = 0; q < 4; q++) {
            __nv_bfloat162 h = *(__nv_bfloat162*)&w[q];
            float f0 = __low2float(h), f1 = __high2float(h);
            f0 = f0 * (1.f + a2 * f0 + a3 * f0 * f0);
            f1 = f1 * (1.f + a2 * f1 + a3 * f1 * f1);
            __nv_bfloat162 o = __floats2bfloat162_rn(f0, f1);
            w[q] = *(uint32_t*)&o;
        }
        *(uint4*)p = make_uint4(w[0], w[1], w[2], w[3]);
    }
    __syncthreads();

    float acc[4][4][4];
#pragma unroll
    for (int i = 0; i < 4; i++)
#pragma unroll
        for (int j = 0; j < 4; j++)
#pragma unroll
            for (int q = 0; q < 4; q++) acc[i][j][q] = 0.f;

    const uint32_t aLane = (uint32_t)((wm * 64 + (lane & 15)) * YZ_ROWB + (lane >> 4) * 16);
    const int bgq = lane >> 3;
    const uint32_t bLane = (uint32_t)((wn * 32 + (bgq >> 1) * 8 + (lane & 7)) * YZ_ROWB + (bgq & 1) * 16);

#pragma unroll
    for (int ks = 0; ks < 4; ks++) {
        const uint32_t kb = (uint32_t)ks * 32;
        uint32_t A[4][4], Bv[4][2];
#pragma unroll
        for (int i = 0; i < 4; i++)
            ldsm_x4(A[i][0], A[i][1], A[i][2], A[i][3],
                    sA + aLane + (uint32_t)i * (16 * YZ_ROWB) + kb);
#pragma unroll
        for (int jp = 0; jp < 2; jp++)
            ldsm_x4(Bv[jp * 2][0], Bv[jp * 2][1], Bv[jp * 2 + 1][0], Bv[jp * 2 + 1][1],
                    sB + bLane + (uint32_t)jp * (16 * YZ_ROWB) + kb);
#pragma unroll
        for (int i = 0; i < 4; i++)
#pragma unroll
            for (int jj = 0; jj < 4; jj++)
                mma16816(acc[i][jj], A[i], Bv[jj][0], Bv[jj][1]);
    }

    // epilogue: z = c0*rs + c1*acc -> fp16, + GN partials
    const int mloc = wm * 64 + (lane >> 2);
    const int nloc = wn * 32 + (lane & 3) * 2;
    float rsv[4][2];
#pragma unroll
    for (int i = 0; i < 4; i++)
#pragma unroll
        for (int h = 0; h < 2; h++)
            rsv[i][h] = d_wzrs[g * 128 + mloc + i * 16 + h * 8];

    __half* zb = d_z16 + ((size_t)(b * 1024 + g * 128)) * 1024;
    float ls = 0.f, lss = 0.f;
#pragma unroll
    for (int i = 0; i < 4; i++)
#pragma unroll
        for (int jj = 0; jj < 4; jj++)
#pragma unroll
            for (int h = 0; h < 2; h++) {
                float z0 = c0 * rsv[i][h] + c1 * acc[i][jj][2 * h + 0];
                float z1 = c0 * rsv[i][h] + c1 * acc[i][jj][2 * h + 1];
                ls += z0 + z1;
                lss += z0 * z0 + z1 * z1;
                int oc = mloc + i * 16 + h * 8;
                int n  = nloc + jj * 8;
                *(__half2*)(zb + (size_t)oc * 1024 + n0 + n) = __floats2half2_rn(z0, z1);
            }

#pragma unroll
    for (int off = 16; off > 0; off >>= 1) {
        ls  += __shfl_down_sync(0xffffffffu, ls, off);
        lss += __shfl_down_sync(0xffffffffu, lss, off);
    }
    __shared__ float red[2][8];
    if (lane == 0) { red[0][wid] = ls; red[1][wid] = lss; }
    __syncthreads();
    if (tid == 0) {
        float S = 0.f, SS = 0.f;
#pragma unroll
        for (int i = 0; i < 8; i++) { S += red[0][i]; SS += red[1][i]; }
        atomicAdd(&d_gn[bgidx * 2 + 0], S);
        atomicAdd(&d_gn[bgidx * 2 + 1], SS);
    }
}

// =====================================================================
// finish: out = (z - mean)*rstd*gn_w + gn_b + x   (z in fp16)
// =====================================================================
__global__ void __launch_bounds__(256) k_finish(
    const float* __restrict__ x, const float* __restrict__ gn_w,
    const float* __restrict__ gn_b, float* __restrict__ out)
{
    int i4 = blockIdx.x * 256 + threadIdx.x;
    if (i4 >= (B_ * C_ * HW_) / 4) return;
    size_t idx = (size_t)i4 * 4;
    int ch = (int)((idx >> 10) & 1023);
    int b  = (int)(idx >> 20);
    int bg = b * 8 + (ch >> 7);
    const float invN = 1.0f / 131072.0f;
    float s  = d_gn[bg * 2 + 0];
    float ss = d_gn[bg * 2 + 1];
    float mean = s * invN;
    float var  = ss * invN - mean * mean;
    float rstd = rsqrtf(var + 1e-5f);
    float a = gn_w[ch] * rstd;
    float c = gn_b[ch] - mean * a;
    uint2 zr = *(const uint2*)&d_z16[idx];
    float2 z01 = __half22float2(*(__half2*)&zr.x);
    float2 z23 = __half22float2(*(__half2*)&zr.y);
    float4 xv = *(const float4*)&x[idx];
    float4 o;
    o.x = z01.x * a + c + xv.x;
    o.y = z01.y * a + c + xv.y;
    o.z = z23.x * a + c + xv.z;
    o.w = z23.y * a + c + xv.w;
    *(float4*)&out[idx] = o;
}

// =====================================================================
extern "C" void kernel_launch(void* const* d_in, const int* in_sizes, int n_in,
                              void* d_out, int out_size)
{
    const float* x   = (const float*)d_in[0];
    const float* Wt  = (const float*)d_in[1];
    const float* Wp  = (const float*)d_in[2];
    const float* Wg  = (const float*)d_in[3];
    const float* Wz  = (const float*)d_in[4];
    const float* gnw = (const float*)d_in[5];
    const float* gnb = (const float*)d_in[6];
    float* out = (float*)d_out;

    cudaFuncSetAttribute(k_gemm_t,  cudaFuncAttributeMaxDynamicSharedMemorySize, 2 * T_STG);
    cudaFuncSetAttribute(k_gemm_pg, cudaFuncAttributeMaxDynamicSharedMemorySize, 2 * PG_STG);

    k_prep<<<1602, 256>>>(Wt, Wp, Wg, Wz);
    k_transX<<<dim3(32, 8, 16), 256>>>(x);
    k_s0<<<128, 256>>>();

    k_gemm_t<<<dim3(8, 4, 16), 256, 2 * T_STG>>>();
    k_gemm_pg<<<dim3(8, 4, 16), 512, 2 * PG_STG>>>();

    k_yz<<<dim3(8, 8, 16), 256, 2 * YZ_BOFF>>>();

    int nblk5 = (B_ * C_ * HW_ / 4 + 255) / 256;
    k_finish<<<nblk5, 256>>>(x, gnw, gnb, out);
}

// round 9
// speedup vs baseline: 5.1782x; 1.0147x over previous
#include <cuda_runtime.h>
#include <cuda_bf16.h>
#include <cuda_fp16.h>
#include <cuda_fp8.h>
#include <cstdint>
#include <math.h>

typedef unsigned long long ull;

#define B_  16
#define C_  1024
#define P_  512
#define HW_ 1024
#define G_  8

#define WSCALE     64.0f
#define INV_WSCALE 0.015625f

// ---------------- scratch (static device globals; no allocation) ----------------
__device__ __half d_z16[(size_t)B_ * C_ * HW_];        // 32 MB fp16
__device__ float d_S[B_ * G_ * 4];                     // moment sums; S0 exact
__device__ float d_gn[B_ * G_ * 2];                    // GN sum / sumsq
__device__ float d_xsum[B_ * C_];                      // per (b,c) spatial sums
__device__ float d_wgsum[G_ * C_];                     // per (g,c) Wg row sums
__device__ float d_wzrs[G_ * 128];                     // rowsum of Wz per (g,oc)

// quantized operands
__device__ uint8_t d_W8[3u * 512u * 1024u];            // fp8 W (x64)
__device__ uint8_t d_XT8[(size_t)B_ * 1024u * 1024u];  // fp8 X^T [b][n][k]
__device__ __nv_bfloat16 d_Wz16[G_ * 128 * 64];        // bf16 Wz

// ---------------- PTX helpers ----------------
__device__ __forceinline__ uint32_t smem_u32(const void* p) {
    uint32_t a;
    asm("{ .reg .u64 t; cvta.to.shared.u64 t, %1; cvt.u32.u64 %0, t; }" : "=r"(a) : "l"(p));
    return a;
}
#define CP_ASYNC16(sa, ga) \
    asm volatile("cp.async.cg.shared.global [%0], [%1], 16;" :: "r"(sa), "l"(ga))
#define CP_COMMIT()   asm volatile("cp.async.commit_group;" ::: "memory")
#define CP_WAIT(n)    asm volatile("cp.async.wait_group %0;" :: "n"(n) : "memory")

__device__ __forceinline__ void ldsm_x4(uint32_t& r0, uint32_t& r1, uint32_t& r2, uint32_t& r3,
                                        uint32_t addr) {
    asm volatile("ldmatrix.sync.aligned.m8n8.x4.shared.b16 {%0,%1,%2,%3}, [%4];"
                 : "=r"(r0), "=r"(r1), "=r"(r2), "=r"(r3) : "r"(addr));
}
__device__ __forceinline__ void mma16832(float* c, const uint32_t* a, uint32_t b0, uint32_t b1) {
    asm volatile("mma.sync.aligned.m16n8k32.row.col.f32.e4m3.e4m3.f32 "
                 "{%0,%1,%2,%3}, {%4,%5,%6,%7}, {%8,%9}, {%0,%1,%2,%3};"
                 : "+f"(c[0]), "+f"(c[1]), "+f"(c[2]), "+f"(c[3])
                 : "r"(a[0]), "r"(a[1]), "r"(a[2]), "r"(a[3]), "r"(b0), "r"(b1));
}
__device__ __forceinline__ void mma16816(float* c, const uint32_t* a, uint32_t b0, uint32_t b1) {
    asm volatile("mma.sync.aligned.m16n8k16.row.col.f32.bf16.bf16.f32 "
                 "{%0,%1,%2,%3}, {%4,%5,%6,%7}, {%8,%9}, {%0,%1,%2,%3};"
                 : "+f"(c[0]), "+f"(c[1]), "+f"(c[2]), "+f"(c[3])
                 : "r"(a[0]), "r"(a[1]), "r"(a[2]), "r"(a[3]), "r"(b0), "r"(b1));
}
__device__ __forceinline__ uint8_t to_e4m3(float v) {
    return (uint8_t)__nv_cvt_float_to_fp8(v, __NV_SATFINITE, __NV_E4M3);
}

// =====================================================================
// k_prep: fused prepass — roles by blockIdx.x
// =====================================================================
__global__ void __launch_bounds__(256) k_prep(
    const float* __restrict__ Wt, const float* __restrict__ Wp,
    const float* __restrict__ Wg, const float* __restrict__ Wz)
{
    int bx = blockIdx.x, tid = threadIdx.x;
    if (bx < 1536) {
        int w = bx >> 9, inner = bx & 511;
        const float* W = (w == 0) ? Wt : (w == 1) ? Wp : Wg;
        size_t idx = ((size_t)inner * 256 + tid) * 4;
        float4 v = *(const float4*)&W[idx];
        uint32_t pk = (uint32_t)to_e4m3(v.x * WSCALE)
                    | ((uint32_t)to_e4m3(v.y * WSCALE) << 8)
                    | ((uint32_t)to_e4m3(v.z * WSCALE) << 16)
                    | ((uint32_t)to_e4m3(v.w * WSCALE) << 24);
        *(uint32_t*)(d_W8 + (size_t)w * 524288u + idx) = pk;
    } else if (bx == 1536) {
        for (int i = tid; i < B_ * C_; i += 256) d_xsum[i] = 0.f;
        for (int i = tid; i < 512; i += 256)     d_S[i]    = 0.f;
        if (tid < 256)                            d_gn[tid] = 0.f;
    } else if (bx < 1569) {
        int idx = bx - 1537;
        int g = idx >> 2, c = (idx & 3) * 256 + tid;
        const float* base = Wg + (size_t)g * 64 * 1024 + c;
        float s = 0.f;
#pragma unroll 8
        for (int r = 0; r < 64; r++) s += base[(size_t)r * 1024];
        d_wgsum[g * 1024 + c] = s;
    } else if (bx < 1601) {
        int idx = bx - 1569;
        int base = idx * 2048 + tid * 8;
        float4 v0 = *(const float4*)&Wz[base];
        float4 v1 = *(const float4*)&Wz[base + 4];
        __nv_bfloat162 h0 = __floats2bfloat162_rn(v0.x, v0.y);
        __nv_bfloat162 h1 = __floats2bfloat162_rn(v0.z, v0.w);
        __nv_bfloat162 h2 = __floats2bfloat162_rn(v1.x, v1.y);
        __nv_bfloat162 h3 = __floats2bfloat162_rn(v1.z, v1.w);
        *(uint4*)(d_Wz16 + base) = make_uint4(*(uint32_t*)&h0, *(uint32_t*)&h1,
                                              *(uint32_t*)&h2, *(uint32_t*)&h3);
    } else {
        for (int oc = tid; oc < 1024; oc += 256) {
            const float* p = Wz + (size_t)oc * 64;
            float s = 0.f;
#pragma unroll
            for (int k = 0; k < 64; k++) s += p[k];
            d_wzrs[oc] = s;
        }
    }
}

// =====================================================================
// X transpose -> fp8 [b][n][k], + exact fp32 channel sums
// =====================================================================
__global__ void __launch_bounds__(256) k_transX(const float* __restrict__ x)
{
    __shared__ float Xs[32][132];
    int k0 = blockIdx.x * 32;
    int n0 = blockIdx.y * 128;
    int b  = blockIdx.z;
    int tid = threadIdx.x;
    const float* xb = x + ((size_t)b * 1024 + k0) * 1024 + n0;
#pragma unroll
    for (int i = 0; i < 4; i++) {
        int slot = tid + i * 256;
        int r  = slot >> 5;
        int c4 = (slot & 31) * 4;
        *(float4*)&Xs[r][c4] = *(const float4*)&xb[(size_t)r * 1024 + c4];
    }
    __syncthreads();

    {
        int r = tid >> 3, q = tid & 7;
        float s = 0.f;
#pragma unroll
        for (int c = 0; c < 16; c++) s += Xs[r][q * 16 + c];
        s += __shfl_down_sync(0xffffffffu, s, 4);
        s += __shfl_down_sync(0xffffffffu, s, 2);
        s += __shfl_down_sync(0xffffffffu, s, 1);
        if (q == 0) atomicAdd(&d_xsum[b * 1024 + k0 + r], s);
    }

    int n  = tid >> 1;
    int kh = (tid & 1) * 16;
    uint32_t pk[4];
#pragma unroll
    for (int j = 0; j < 4; j++) {
        pk[j] = (uint32_t)to_e4m3(Xs[kh + 4 * j + 0][n])
              | ((uint32_t)to_e4m3(Xs[kh + 4 * j + 1][n]) << 8)
              | ((uint32_t)to_e4m3(Xs[kh + 4 * j + 2][n]) << 16)
              | ((uint32_t)to_e4m3(Xs[kh + 4 * j + 3][n]) << 24);
    }
    size_t off = ((size_t)b * 1024 + n0 + n) * 1024 + k0 + kh;
    *(uint4*)(d_XT8 + off) = make_uint4(pk[0], pk[1], pk[2], pk[3]);
}

// =====================================================================
// Exact S0[b][g] = sum_c wgsum[g][c] * xsum[b][c]
// =====================================================================
__global__ void __launch_bounds__(256) k_s0()
{
    int bg = blockIdx.x;
    int b = bg >> 3, g = bg & 7;
    int tid = threadIdx.x;
    float s = 0.f;
    for (int c = tid; c < 1024; c += 256)
        s += d_wgsum[g * 1024 + c] * d_xsum[b * 1024 + c];
#pragma unroll
    for (int off = 16; off > 0; off >>= 1)
        s += __shfl_down_sync(0xffffffffu, s, off);
    __shared__ float red[8];
    if ((tid & 31) == 0) red[tid >> 5] = s;
    __syncthreads();
    if (tid == 0) {
        float S = 0.f;
#pragma unroll
        for (int i = 0; i < 8; i++) S += red[i];
        d_S[bg * 4 + 0] = S;
    }
}

// =====================================================================
// GEMM-PG (fp8): CTA 128m x 128n, 512 thr / 16 warps (warp 32x32),
// 3-stage cp.async pipeline; epilogue reduces S1..S3 via atomicAdd.
// =====================================================================
#define NCH        16
#define ROWB       80
#define TILE_B     10240
#define PG_STG     30720

__device__ __forceinline__ void pg_load_chunk(
    uint32_t sb, const uint8_t* gAp, const uint8_t* gAg,
    const uint8_t* gB, int k0, int tid)
{
    const uint8_t* srcs[3] = {gAp, gAg, gB};
#pragma unroll
    for (int i = 0; i < 3; i++) {
        int r = tid >> 2, u = tid & 3;
        uint32_t dst = sb + (uint32_t)i * TILE_B + (uint32_t)r * ROWB + (uint32_t)u * 16;
        CP_ASYNC16(dst, (const void*)(srcs[i] + (size_t)r * 1024 + k0 + u * 16));
    }
}

__global__ void __launch_bounds__(512, 1) k_gemm_pg()
{
    extern __shared__ char smraw[];
    uint32_t sbase = smem_u32(smraw);

    const int tid  = threadIdx.x;
    const int wid  = tid >> 5;
    const int lane = tid & 31;
    const int wm   = wid & 3;
    const int wn   = wid >> 2;

    const int n0 = blockIdx.x * 128;
    const int m0 = blockIdx.y * 128;
    const int b  = blockIdx.z;

    const uint8_t* gAp = d_W8 + 1u * 524288u + (size_t)m0 * 1024;
    const uint8_t* gAg = d_W8 + 2u * 524288u + (size_t)m0 * 1024;
    const uint8_t* gB  = d_XT8 + ((size_t)b * 1024 + n0) * 1024;

    float accp[2][4][4], accg[2][4][4];
#pragma unroll
    for (int i = 0; i < 2; i++)
#pragma unroll
        for (int j = 0; j < 4; j++)
#pragma unroll
            for (int q = 0; q < 4; q++) { accp[i][j][q] = 0.f; accg[i][j][q] = 0.f; }

    const uint32_t aLane = (uint32_t)((wm * 32 + (lane & 15)) * ROWB + (lane >> 4) * 16);
    const int bgrp = lane >> 3;
    const uint32_t bLane = (uint32_t)((wn * 32 + (bgrp >> 1) * 8 + (lane & 7)) * ROWB + (bgrp & 1) * 16);

    pg_load_chunk(sbase, gAp, gAg, gB, 0, tid);
    CP_COMMIT();
    pg_load_chunk(sbase + PG_STG, gAp, gAg, gB, 64, tid);
    CP_COMMIT();

    int stg = 0;
    for (int j = 0; j < NCH; j++) {
        if (j + 1 < NCH) CP_WAIT(1); else CP_WAIT(0);
        __syncthreads();
        if (j + 2 < NCH) {
            int ns = stg + 2; if (ns >= 3) ns -= 3;
            pg_load_chunk(sbase + (uint32_t)ns * PG_STG, gAp, gAg, gB, (j + 2) * 64, tid);
            CP_COMMIT();
        }
        const uint32_t sb = sbase + (uint32_t)stg * PG_STG;
#pragma unroll
        for (int s = 0; s < 2; s++) {
            const uint32_t kb = (uint32_t)s * 32;
            uint32_t Ap[2][4], Ag[2][4], Bv[4][2];
#pragma unroll
            for (int i = 0; i < 2; i++) {
                ldsm_x4(Ap[i][0], Ap[i][1], Ap[i][2], Ap[i][3],
                        sb + 0 * TILE_B + aLane + (uint32_t)i * (16 * ROWB) + kb);
                ldsm_x4(Ag[i][0], Ag[i][1], Ag[i][2], Ag[i][3],
                        sb + 1 * TILE_B + aLane + (uint32_t)i * (16 * ROWB) + kb);
            }
#pragma unroll
            for (int jp = 0; jp < 2; jp++)
                ldsm_x4(Bv[jp * 2][0], Bv[jp * 2][1], Bv[jp * 2 + 1][0], Bv[jp * 2 + 1][1],
                        sb + 2 * TILE_B + bLane + (uint32_t)jp * (16 * ROWB) + kb);
#pragma unroll
            for (int i = 0; i < 2; i++)
#pragma unroll
                for (int jj = 0; jj < 4; jj++) {
                    mma16832(accp[i][jj], Ap[i], Bv[jj][0], Bv[jj][1]);
                    mma16832(accg[i][jj], Ag[i], Bv[jj][0], Bv[jj][1]);
                }
        }
        if (++stg == 3) stg = 0;
    }

    {
        float s1 = 0.f, s2 = 0.f, s3 = 0.f;
#pragma unroll
        for (int i = 0; i < 2; i++)
#pragma unroll
            for (int jj = 0; jj < 4; jj++)
#pragma unroll
                for (int q = 0; q < 4; q++) {
                    float pv = accp[i][jj][q] * INV_WSCALE;
                    float gv = accg[i][jj][q] * INV_WSCALE;
                    float t1 = pv * gv; s1 += t1;
                    t1 *= pv; s2 += t1;
                    t1 *= pv; s3 += t1;
                }
#pragma unroll
        for (int off = 16; off > 0; off >>= 1) {
            s1 += __shfl_down_sync(0xffffffffu, s1, off);
            s2 += __shfl_down_sync(0xffffffffu, s2, off);
            s3 += __shfl_down_sync(0xffffffffu, s3, off);
        }
        if (lane == 0) {
            int g = (m0 >> 6) + (wm >> 1);
            float* Sp = d_S + (b * 8 + g) * 4;
            atomicAdd(Sp + 1, s1);
            atomicAdd(Sp + 2, s2);
            atomicAdd(Sp + 3, s3);
        }
    }
}

// =====================================================================
// GEMM-TZ (fp8 + fused z): t = Wt @ X (CTA 128x128, warp 64x32, 3-stage),
// then IN-KERNEL: y'' = t(1 + a2 t + a3 t^2) staged [n][ch] in smem,
// z = c0*rowsum(Wz) + c1*(Wz @ y'') via bf16 HMMA, written fp16 + GN sums.
// CTA's 128 m-rows = exactly 2 groups (K=64 each).
// =====================================================================
#define T_STG     20480
#define AZ_OFF    0
#define TS_OFF    36864
#define ZT_STRIDE 18432          // 128 rows * 144 B
#define ROWZ      144
#define TZ_SMEM   73728

__device__ __forceinline__ void t_load_chunk(
    uint32_t sb, const uint8_t* gA, const uint8_t* gB, int k0, int tid)
{
#pragma unroll
    for (int i = 0; i < 4; i++) {
        int unit = tid + i * 256;
        int tile = unit >> 9;
        int rem  = unit & 511;
        int r = rem >> 2, u = rem & 3;
        uint32_t dst = sb + (uint32_t)tile * TILE_B + (uint32_t)r * ROWB + (uint32_t)u * 16;
        const uint8_t* src = (tile == 0 ? gA : gB) + (size_t)r * 1024 + k0 + u * 16;
        CP_ASYNC16(dst, (const void*)src);
    }
}

__global__ void __launch_bounds__(256, 2) k_gemm_tz()
{
    extern __shared__ char smraw[];
    uint32_t sbase = smem_u32(smraw);

    const int tid  = threadIdx.x;
    const int wid  = tid >> 5;
    const int lane = tid & 31;
    const int wm   = wid & 1;
    const int wn   = wid >> 1;

    const int n0 = blockIdx.x * 128;
    const int m0 = blockIdx.y * 128;
    const int b  = blockIdx.z;

    const uint8_t* gA = d_W8 + (size_t)m0 * 1024;
    const uint8_t* gB = d_XT8 + ((size_t)b * 1024 + n0) * 1024;

    float acc[4][4][4];
#pragma unroll
    for (int i = 0; i < 4; i++)
#pragma unroll
        for (int j = 0; j < 4; j++)
#pragma unroll
            for (int q = 0; q < 4; q++) acc[i][j][q] = 0.f;

    const uint32_t aLane = (uint32_t)((wm * 64 + (lane & 15)) * ROWB + (lane >> 4) * 16);
    const int bg = lane >> 3;
    const uint32_t bLane = (uint32_t)((wn * 32 + (bg >> 1) * 8 + (lane & 7)) * ROWB + (bg & 1) * 16);

    t_load_chunk(sbase, gA, gB, 0, tid);
    CP_COMMIT();
    t_load_chunk(sbase + T_STG, gA, gB, 64, tid);
    CP_COMMIT();

    int stg = 0;
    for (int j = 0; j < NCH; j++) {
        if (j + 1 < NCH) CP_WAIT(1); else CP_WAIT(0);
        __syncthreads();
        if (j + 2 < NCH) {
            int ns = stg + 2; if (ns >= 3) ns -= 3;
            t_load_chunk(sbase + (uint32_t)ns * T_STG, gA, gB, (j + 2) * 64, tid);
            CP_COMMIT();
        }
        const uint32_t sb = sbase + (uint32_t)stg * T_STG;
#pragma unroll
        for (int s = 0; s < 2; s++) {
            const uint32_t kb = (uint32_t)s * 32;
            uint32_t A[4][4], Bv[4][2];
#pragma unroll
            for (int i = 0; i < 4; i++)
                ldsm_x4(A[i][0], A[i][1], A[i][2], A[i][3],
                        sb + aLane + (uint32_t)i * (16 * ROWB) + kb);
#pragma unroll
            for (int jp = 0; jp < 2; jp++)
                ldsm_x4(Bv[jp * 2][0], Bv[jp * 2][1], Bv[jp * 2 + 1][0], Bv[jp * 2 + 1][1],
                        sb + TILE_B + bLane + (uint32_t)jp * (16 * ROWB) + kb);
#pragma unroll
            for (int i = 0; i < 4; i++)
#pragma unroll
                for (int jj = 0; jj < 4; jj++)
                    mma16832(acc[i][jj], A[i], Bv[jj][0], Bv[jj][1]);
        }
        if (++stg == 3) stg = 0;
    }
    __syncthreads();        // all warps done reading stage smem

    const float tg   = 2.0f * 1e-4f;
    const float beta = expf(-tg);

    // ---- epilogue A: y'' transform + transposed smem stage [n][ch] ----
    {
        const int gidx = (b * 8) + (m0 >> 6) + wm;     // warp's group
        const float c1 = beta * tg * d_S[gidx * 4 + 1];
        const float c2 = beta * (tg * tg * 0.5f) * d_S[gidx * 4 + 2];
        const float c3 = beta * (tg * tg * tg * (1.f / 6.f)) * d_S[gidx * 4 + 3];
        const float a2 = c2 / c1, a3 = c3 / c1;

        char* Tsb = smraw + TS_OFF + wm * ZT_STRIDE;
        const int mq = lane >> 2;
        const int nq = (lane & 3) * 2;
#pragma unroll
        for (int i = 0; i < 4; i++)
#pragma unroll
            for (int jj = 0; jj < 4; jj++)
#pragma unroll
                for (int q = 0; q < 4; q++) {
                    int chl = (i * 16 + mq + ((q >> 1) << 3)) & 63;
                    int n   = wn * 32 + jj * 8 + nq + (q & 1);
                    float t = acc[i][jj][q] * INV_WSCALE;
                    float y = t * (1.f + a2 * t + a3 * t * t);
                    *(__nv_bfloat16*)(Tsb + n * ROWZ + chl * 2) = __float2bfloat16(y);
                }
    }
    // ---- epilogue B: async-load Wz tiles for the 2 groups ----
    {
        const int gb = (m0 >> 6);
#pragma unroll
        for (int i = 0; i < 8; i++) {
            int unit = tid + i * 256;             // 0..2047
            int tile = unit >> 10;
            int rem  = unit & 1023;
            int r = rem >> 3, u = rem & 7;
            CP_ASYNC16(sbase + AZ_OFF + (uint32_t)tile * ZT_STRIDE + (uint32_t)r * ROWZ + (uint32_t)u * 16,
                       (const void*)(d_Wz16 + (gb + tile) * 8192 + r * 64 + u * 8));
        }
        CP_COMMIT();
        CP_WAIT(0);
        __syncthreads();
    }
    // ---- epilogue C: z-GEMM, 2 jobs per warp (job = 64oc x 32n of one group) ----
#pragma unroll
    for (int jb = 0; jb < 2; jb++) {
        const int job  = wid * 2 + jb;            // 0..15
        const int gloc = job >> 3;
        const int och  = (job & 7) >> 2;
        const int nq   = job & 3;
        const int g    = (m0 >> 6) + gloc;
        const int gidx = b * 8 + g;
        const float c0 = beta * d_S[gidx * 4 + 0];
        const float c1 = beta * tg * d_S[gidx * 4 + 1];

        const uint32_t aBase = sbase + AZ_OFF + (uint32_t)gloc * ZT_STRIDE;
        const uint32_t bBase = sbase + TS_OFF + (uint32_t)gloc * ZT_STRIDE;
        const uint32_t aL = (uint32_t)((och * 64 + (lane & 15)) * ROWZ + (lane >> 4) * 16);
        const int bq = lane >> 3;
        const uint32_t bL = (uint32_t)((nq * 32 + (bq >> 1) * 8 + (lane & 7)) * ROWZ + (bq & 1) * 16);

        float az[4][4][4];
#pragma unroll
        for (int i = 0; i < 4; i++)
#pragma unroll
            for (int jj = 0; jj < 4; jj++)
#pragma unroll
                for (int q = 0; q < 4; q++) az[i][jj][q] = 0.f;

#pragma unroll
        for (int ks = 0; ks < 4; ks++) {
            const uint32_t kb = (uint32_t)ks * 32;
            uint32_t A[4][4], Bv[4][2];
#pragma unroll
            for (int i = 0; i < 4; i++)
                ldsm_x4(A[i][0], A[i][1], A[i][2], A[i][3],
                        aBase + aL + (uint32_t)i * (16 * ROWZ) + kb);
#pragma unroll
            for (int jp = 0; jp < 2; jp++)
                ldsm_x4(Bv[jp * 2][0], Bv[jp * 2][1], Bv[jp * 2 + 1][0], Bv[jp * 2 + 1][1],
                        bBase + bL + (uint32_t)jp * (16 * ROWZ) + kb);
#pragma unroll
            for (int i = 0; i < 4; i++)
#pragma unroll
                for (int jj = 0; jj < 4; jj++)
                    mma16816(az[i][jj], A[i], Bv[jj][0], Bv[jj][1]);
        }

        // write z (fp16) + GN partials for this job
        const int mloc = och * 64 + (lane >> 2);
        const int nloc = nq * 32 + (lane & 3) * 2;
        float rsv[4][2];
#pragma unroll
        for (int i = 0; i < 4; i++)
#pragma unroll
            for (int h = 0; h < 2; h++)
                rsv[i][h] = d_wzrs[g * 128 + mloc + i * 16 + h * 8];

        __half* zb = d_z16 + ((size_t)(b * 1024 + g * 128)) * 1024;
        float ls = 0.f, lss = 0.f;
#pragma unroll
        for (int i = 0; i < 4; i++)
#pragma unroll
            for (int jj = 0; jj < 4; jj++)
#pragma unroll
                for (int h = 0; h < 2; h++) {
                    float z0 = c0 * rsv[i][h] + c1 * az[i][jj][2 * h + 0];
                    float z1 = c0 * rsv[i][h] + c1 * az[i][jj][2 * h + 1];
                    ls += z0 + z1;
                    lss += z0 * z0 + z1 * z1;
                    int oc = mloc + i * 16 + h * 8;
                    int n  = nloc + jj * 8;
                    *(__half2*)(zb + (size_t)oc * 1024 + n0 + n) = __floats2half2_rn(z0, z1);
                }
#pragma unroll
        for (int off = 16; off > 0; off >>= 1) {
            ls  += __shfl_down_sync(0xffffffffu, ls, off);
            lss += __shfl_down_sync(0xffffffffu, lss, off);
        }
        if (lane == 0) {
            atomicAdd(&d_gn[gidx * 2 + 0], ls);
            atomicAdd(&d_gn[gidx * 2 + 1], lss);
        }
    }
}

// =====================================================================
// finish: out = (z - mean)*rstd*gn_w + gn_b + x   (z in fp16)
// =====================================================================
__global__ void __launch_bounds__(256) k_finish(
    const float* __restrict__ x, const float* __restrict__ gn_w,
    const float* __restrict__ gn_b, float* __restrict__ out)
{
    int i4 = blockIdx.x * 256 + threadIdx.x;
    if (i4 >= (B_ * C_ * HW_) / 4) return;
    size_t idx = (size_t)i4 * 4;
    int ch = (int)((idx >> 10) & 1023);
    int b  = (int)(idx >> 20);
    int bg = b * 8 + (ch >> 7);
    const float invN = 1.0f / 131072.0f;
    float s  = d_gn[bg * 2 + 0];
    float ss = d_gn[bg * 2 + 1];
    float mean = s * invN;
    float var  = ss * invN - mean * mean;
    float rstd = rsqrtf(var + 1e-5f);
    float a = gn_w[ch] * rstd;
    float c = gn_b[ch] - mean * a;
    uint2 zr = *(const uint2*)&d_z16[idx];
    float2 z01 = __half22float2(*(__half2*)&zr.x);
    float2 z23 = __half22float2(*(__half2*)&zr.y);
    float4 xv = *(const float4*)&x[idx];
    float4 o;
    o.x = z01.x * a + c + xv.x;
    o.y = z01.y * a + c + xv.y;
    o.z = z23.x * a + c + xv.z;
    o.w = z23.y * a + c + xv.w;
    *(float4*)&out[idx] = o;
}

// =====================================================================
extern "C" void kernel_launch(void* const* d_in, const int* in_sizes, int n_in,
                              void* d_out, int out_size)
{
    const float* x   = (const float*)d_in[0];
    const float* Wt  = (const float*)d_in[1];
    const float* Wp  = (const float*)d_in[2];
    const float* Wg  = (const float*)d_in[3];
    const float* Wz  = (const float*)d_in[4];
    const float* gnw = (const float*)d_in[5];
    const float* gnb = (const float*)d_in[6];
    float* out = (float*)d_out;

    cudaFuncSetAttribute(k_gemm_tz, cudaFuncAttributeMaxDynamicSharedMemorySize, TZ_SMEM);
    cudaFuncSetAttribute(k_gemm_pg, cudaFuncAttributeMaxDynamicSharedMemorySize, 3 * PG_STG);

    k_prep<<<1602, 256>>>(Wt, Wp, Wg, Wz);
    k_transX<<<dim3(32, 8, 16), 256>>>(x);
    k_s0<<<128, 256>>>();

    k_gemm_pg<<<dim3(8, 4, 16), 512, 3 * PG_STG>>>();
    k_gemm_tz<<<dim3(8, 4, 16), 256, TZ_SMEM>>>();

    int nblk5 = (B_ * C_ * HW_ / 4 + 255) / 256;
    k_finish<<<nblk5, 256>>>(x, gnw, gnb, out);
}